// round 15
// baseline (speedup 1.0000x reference)
#include <cuda_runtime.h>
#include <math.h>

#define CB 2
#define CT 8
#define CHEADS 12
#define CD 768
#define CDF 3072
#define CE 8
#define CN 196
#define CS 1568
#define CBS 3136           // B*S
#define CBSP 3200          // padded per-expert row stride (25*128)
#define C3D 2304
#define CEPART ((size_t)CE*CBSP*CD)   // one k-part image of expert outputs
#define CXPART ((size_t)CBS*CD)       // one k-part image of dense outputs

// gemm smem per stage: raw A[128][36] + raw B[32][136]; THREE stages (cp.async ring)
#define SM_A  (128*36)
#define SM_B  (32*136)
#define STG_FLOATS (SM_A + SM_B)
#define TC_SMEM_BYTES (3*STG_FLOATS*4)

// attention smem (floats): Ks[2][64][68], Vs[2][64][72], Ps[64][68], tbs
#define ATT_KS0  0
#define ATT_KS1  (64*68)
#define ATT_VS0  (2*64*68)
#define ATT_VS1  (2*64*68 + 64*72)
#define ATT_PS   (2*64*68 + 2*64*72)
#define ATT_TBS  (2*64*68 + 2*64*72 + 64*68)
#define ATT_SMEM_BYTES ((ATT_TBS + 16)*4)

// ---------------- scratch (device globals; no allocation allowed) ----------------
__device__ float g_patches[CBS*CD];
__device__ float g_x[CBS*CD];
__device__ float g_h[CBS*CD];
__device__ float g_h2[CBS*CD];
__device__ float g_qkv[CBS*C3D];
__device__ float g_att[CBS*CD];
__device__ float g_he[(size_t)CE*CBSP*CDF];   // expert hidden, slot-indexed (padded)
__device__ float g_moe4[4*CEPART];            // expert output, 4 split-K part images
__device__ float g_p3[3*CXPART];              // dense split-K partials (WO / embed)
__device__ float g_tproj[CB*CD];
__device__ int   g_counts[CE];
__device__ int   g_tok[CE*CBS];              // slot -> token row
__device__ int   g_slot[CBS*2];              // token -> its 2 slots (padded index)
__device__ float g_gate[CBS*2];              // token -> its 2 gates

__device__ __forceinline__ float gelu_t(float x){
    return 0.5f*x*(1.0f + tanhf(0.7978845608028654f*(x + 0.044715f*x*x*x)));
}

// mask-based tf32 hi/lo split: hi keeps exactly tf32's 10 explicit mantissa bits
__device__ __forceinline__ void split1(float v, unsigned& h, unsigned& l){
    unsigned hu = __float_as_uint(v) & 0xFFFFE000u;
    h = hu;
    l = __float_as_uint(v - __uint_as_float(hu));
}

#define MMA_TF32(c, A0,A1,A2,A3, B0,B1) \
    asm volatile("mma.sync.aligned.m16n8k8.row.col.f32.tf32.tf32.f32 " \
        "{%0,%1,%2,%3}, {%4,%5,%6,%7}, {%8,%9}, {%0,%1,%2,%3};" \
        : "+f"((c)[0]),"+f"((c)[1]),"+f"((c)[2]),"+f"((c)[3]) \
        : "r"(A0),"r"(A1),"r"(A2),"r"(A3),"r"(B0),"r"(B1))

__device__ __forceinline__ void cp16(float* dst_smem, const float* src){
    unsigned d = (unsigned)__cvta_generic_to_shared(dst_smem);
    asm volatile("cp.async.cg.shared.global [%0], [%1], 16;" :: "r"(d), "l"(src));
}
#define CP_COMMIT() asm volatile("cp.async.commit_group;" ::: "memory")
#define CP_WAIT1()  asm volatile("cp.async.wait_group 1;" ::: "memory")
#define CP_WAIT0()  asm volatile("cp.async.wait_group 0;" ::: "memory")

// ---------------- patchify ----------------
__global__ __launch_bounds__(256) void patchify_k(const float* __restrict__ video,
                                                  float* __restrict__ out){
    int i = blockIdx.x*256 + threadIdx.x;
    if (i >= CBS*CD) return;
    int r = i / CD, pp = i % CD;
    int b = r / CS, s = r % CS;
    int t = s / CN, pi = s % CN;
    int ph = pi / 14, pw = pi % 14;
    int c = pp >> 8, rem = pp & 255, py = rem >> 4, px = rem & 15;
    size_t vi = ((((size_t)b*CT + t)*3 + c)*224 + (ph*16+py))*224 + (pw*16+px);
    out[i] = video[vi];
}

// ---------------- layernorm ----------------
__global__ __launch_bounds__(256) void ln_k(const float* __restrict__ x,
                                            const float* __restrict__ gs,
                                            const float* __restrict__ gb,
                                            float* __restrict__ out){
    int r = blockIdx.x;
    const float* xr = x + (size_t)r*CD;
    int d = threadIdx.x;
    float v0 = xr[d], v1 = xr[d+256], v2 = xr[d+512];
    float s = v0+v1+v2, sq = v0*v0+v1*v1+v2*v2;
    #pragma unroll
    for (int o=16;o;o>>=1){ s += __shfl_xor_sync(0xffffffffu,s,o); sq += __shfl_xor_sync(0xffffffffu,sq,o); }
    __shared__ float rs[8], rq[8];
    int w = threadIdx.x>>5;
    if ((threadIdx.x&31)==0){ rs[w]=s; rq[w]=sq; }
    __syncthreads();
    float ts=0.f, tq=0.f;
    #pragma unroll
    for (int i=0;i<8;i++){ ts+=rs[i]; tq+=rq[i]; }
    float mean = ts*(1.0f/CD);
    float var  = tq*(1.0f/CD) - mean*mean;
    float rstd = rsqrtf(var + 1e-5f);
    float* orow = out + (size_t)r*CD;
    orow[d]     = (v0-mean)*rstd*gs[d]     + gb[d];
    orow[d+256] = (v1-mean)*rstd*gs[d+256] + gb[d+256];
    orow[d+512] = (v2-mean)*rstd*gs[d+512] + gb[d+512];
}

// =====================================================================
// 3xTF32 mma.sync GEMM, cp.async 3-stage ring (round 13 winner, unchanged)
// =====================================================================
__global__ __launch_bounds__(256,2) void tc_gemm(
    int M, int N, int K,
    const float* __restrict__ A,
    const float* __restrict__ Wl, size_t wstride,
    const float* __restrict__ bl, int bstride,
    const float* __restrict__ addFull,
    const float* __restrict__ addRow,
    float* __restrict__ C,
    const int* __restrict__ tok,
    const int* __restrict__ counts,
    int doGelu)
{
    extern __shared__ float smf[];

    const int e = blockIdx.z;
    int Me = M;
    const float* W = Wl;
    const float* bias = bl;
    if (counts){
        Me = counts[e];
        W = Wl + (size_t)e*wstride;
        bias = bl + (size_t)e*bstride;
    }
    const int m0 = blockIdx.y*128;
    if (m0 >= Me) return;
    const int n0 = blockIdx.x*128;
    const int tid = threadIdx.x, wid = tid>>5, lane = tid&31;
    const int wm = (wid>>2)*64;
    const int wn = (wid&3)*32;
    const int g = lane>>2, t4 = lane&3;

    const int rowA = tid>>1, segA = (tid&1)*16;
    const int rowB = tid>>3, segB = (tid&7)*16;

    size_t arow;
    {
        int mm = m0 + rowA;
        if (tok)         arow = (size_t)tok[e*CBS + (mm < Me ? mm : 0)];
        else if (counts) arow = (size_t)e*CBSP + mm;
        else             arow = (size_t)(mm < M ? mm : (M-1));
    }
    const float* apBase = A + arow*(size_t)K + segA;
    const float* bpBase = W + (size_t)rowB*N + n0 + segB;

    float acc[4][4][4];
    #pragma unroll
    for (int i=0;i<4;i++)
        #pragma unroll
        for (int j=0;j<4;j++)
            #pragma unroll
            for (int q=0;q<4;q++) acc[i][j][q] = 0.f;

    const int nc = K/32;

    #pragma unroll
    for (int p=0; p<2; p++){
        float* As = smf + p*STG_FLOATS;
        float* Bs = As + SM_A;
        const float* ap = apBase + p*32;
        const float* bp = bpBase + (size_t)p*32*N;
        #pragma unroll
        for (int i=0;i<4;i++) cp16(As + rowA*36 + segA + i*4, ap + i*4);
        #pragma unroll
        for (int i=0;i<4;i++) cp16(Bs + rowB*136 + segB + i*4, bp + i*4);
        CP_COMMIT();
    }

    for (int c = 0; c < nc; c++){
        CP_WAIT1();
        __syncthreads();
        const int st = c % 3;
        float* As = smf + st*STG_FLOATS;
        float* Bs = As + SM_A;

        if (c+2 < nc){
            const int st2 = (c+2) % 3;
            float* As2 = smf + st2*STG_FLOATS;
            float* Bs2 = As2 + SM_A;
            const float* ap = apBase + (c+2)*32;
            const float* bp = bpBase + (size_t)(c+2)*32*N;
            #pragma unroll
            for (int i=0;i<4;i++) cp16(As2 + rowA*36 + segA + i*4, ap + i*4);
            #pragma unroll
            for (int i=0;i<4;i++) cp16(Bs2 + rowB*136 + segB + i*4, bp + i*4);
        }
        CP_COMMIT();

        #pragma unroll
        for (int ks=0; ks<4; ks++){
            unsigned ahr[4][4], alr[4][4];
            #pragma unroll
            for (int mi=0;mi<4;mi++){
                int r0 = (wm + mi*16 + g)*36 + ks*8 + t4;
                int r1 = r0 + 8*36;
                split1(As[r0],   ahr[mi][0], alr[mi][0]);
                split1(As[r1],   ahr[mi][1], alr[mi][1]);
                split1(As[r0+4], ahr[mi][2], alr[mi][2]);
                split1(As[r1+4], ahr[mi][3], alr[mi][3]);
            }
            #pragma unroll
            for (int ni=0;ni<4;ni++){
                int b0i = (ks*8 + t4)*136 + wn + ni*8 + g;
                int b1i = b0i + 4*136;
                unsigned bh0, bl0, bh1, bl1;
                split1(Bs[b0i], bh0, bl0);
                split1(Bs[b1i], bh1, bl1);
                #pragma unroll
                for (int mi=0;mi<4;mi++){
                    MMA_TF32(acc[mi][ni], ahr[mi][0],ahr[mi][1],ahr[mi][2],ahr[mi][3], bl0,bl1);
                    MMA_TF32(acc[mi][ni], alr[mi][0],alr[mi][1],alr[mi][2],alr[mi][3], bh0,bh1);
                    MMA_TF32(acc[mi][ni], ahr[mi][0],ahr[mi][1],ahr[mi][2],ahr[mi][3], bh0,bh1);
                }
            }
        }
    }

    #pragma unroll
    for (int mi=0;mi<4;mi++){
        #pragma unroll
        for (int half=0; half<2; half++){
            int mm = m0 + wm + mi*16 + g + half*8;
            if (!counts && mm >= M) continue;
            size_t crow = counts ? ((size_t)e*CBSP + mm) : (size_t)mm;
            float* cp = C + crow*N;
            const float* afp = addFull ? (addFull + crow*N) : (const float*)0;
            const float* arp = addRow  ? (addRow + (size_t)(mm % CS)*N) : (const float*)0;
            #pragma unroll
            for (int ni=0;ni<4;ni++){
                int col = n0 + wn + ni*8 + 2*t4;
                float v0 = acc[mi][ni][half*2+0] + bias[col];
                float v1 = acc[mi][ni][half*2+1] + bias[col+1];
                if (arp){ v0 += arp[col]; v1 += arp[col+1]; }
                if (afp){ v0 += afp[col]; v1 += afp[col+1]; }
                if (doGelu){ v0 = gelu_t(v0); v1 = gelu_t(v1); }
                float2 vv; vv.x = v0; vv.y = v1;
                *(float2*)(cp + col) = vv;
            }
        }
    }
}

// =====================================================================
// Dense split-K x3 GEMM, hardcoded N=768, K=768, Ksub=256 (8 chunks).
// blockIdx.x = kp*6 + nx. Pure GEMM: raw partials, no bias (epilogue adds).
// Used for WO and embed (both K=768 -> N=768 dense).
// =====================================================================
__global__ __launch_bounds__(256,2) void tc_gemm_sk3(
    const float* __restrict__ A,     // [CBS][768]
    const float* __restrict__ W,     // [768][768]
    float* __restrict__ C)           // 3 part images of [CBS][768]
{
    extern __shared__ float smf[];

    const int kp = blockIdx.x / 6;
    const int n0 = (blockIdx.x % 6)*128;
    const int m0 = blockIdx.y*128;
    const int tid = threadIdx.x, wid = tid>>5, lane = tid&31;
    const int wm = (wid>>2)*64;
    const int wn = (wid&3)*32;
    const int g = lane>>2, t4 = lane&3;

    const int rowA = tid>>1, segA = (tid&1)*16;
    const int rowB = tid>>3, segB = (tid&7)*16;

    int mmL = m0 + rowA; if (mmL >= CBS) mmL = CBS-1;
    const float* apBase = A + (size_t)mmL*CD + kp*256 + segA;
    const float* bpBase = W + (size_t)(kp*256 + rowB)*CD + n0 + segB;

    float acc[4][4][4];
    #pragma unroll
    for (int i=0;i<4;i++)
        #pragma unroll
        for (int j=0;j<4;j++)
            #pragma unroll
            for (int q=0;q<4;q++) acc[i][j][q] = 0.f;

    #pragma unroll
    for (int p=0; p<2; p++){
        float* As = smf + p*STG_FLOATS;
        float* Bs = As + SM_A;
        const float* ap = apBase + p*32;
        const float* bp = bpBase + (size_t)p*32*CD;
        #pragma unroll
        for (int i=0;i<4;i++) cp16(As + rowA*36 + segA + i*4, ap + i*4);
        #pragma unroll
        for (int i=0;i<4;i++) cp16(Bs + rowB*136 + segB + i*4, bp + i*4);
        CP_COMMIT();
    }

    for (int c = 0; c < 8; c++){
        CP_WAIT1();
        __syncthreads();
        const int st = c % 3;
        float* As = smf + st*STG_FLOATS;
        float* Bs = As + SM_A;

        if (c+2 < 8){
            const int st2 = (c+2) % 3;
            float* As2 = smf + st2*STG_FLOATS;
            float* Bs2 = As2 + SM_A;
            const float* ap = apBase + (c+2)*32;
            const float* bp = bpBase + (size_t)(c+2)*32*CD;
            #pragma unroll
            for (int i=0;i<4;i++) cp16(As2 + rowA*36 + segA + i*4, ap + i*4);
            #pragma unroll
            for (int i=0;i<4;i++) cp16(Bs2 + rowB*136 + segB + i*4, bp + i*4);
        }
        CP_COMMIT();

        #pragma unroll
        for (int ks=0; ks<4; ks++){
            unsigned ahr[4][4], alr[4][4];
            #pragma unroll
            for (int mi=0;mi<4;mi++){
                int r0 = (wm + mi*16 + g)*36 + ks*8 + t4;
                int r1 = r0 + 8*36;
                split1(As[r0],   ahr[mi][0], alr[mi][0]);
                split1(As[r1],   ahr[mi][1], alr[mi][1]);
                split1(As[r0+4], ahr[mi][2], alr[mi][2]);
                split1(As[r1+4], ahr[mi][3], alr[mi][3]);
            }
            #pragma unroll
            for (int ni=0;ni<4;ni++){
                int b0i = (ks*8 + t4)*136 + wn + ni*8 + g;
                int b1i = b0i + 4*136;
                unsigned bh0, bl0, bh1, bl1;
                split1(Bs[b0i], bh0, bl0);
                split1(Bs[b1i], bh1, bl1);
                #pragma unroll
                for (int mi=0;mi<4;mi++){
                    MMA_TF32(acc[mi][ni], ahr[mi][0],ahr[mi][1],ahr[mi][2],ahr[mi][3], bl0,bl1);
                    MMA_TF32(acc[mi][ni], alr[mi][0],alr[mi][1],alr[mi][2],alr[mi][3], bh0,bh1);
                    MMA_TF32(acc[mi][ni], ahr[mi][0],ahr[mi][1],ahr[mi][2],ahr[mi][3], bh0,bh1);
                }
            }
        }
    }

    float* Cp = C + (size_t)kp*CXPART;
    #pragma unroll
    for (int mi=0;mi<4;mi++){
        #pragma unroll
        for (int half=0; half<2; half++){
            int mm = m0 + wm + mi*16 + g + half*8;
            if (mm >= CBS) continue;
            float* cp = Cp + (size_t)mm*CD;
            #pragma unroll
            for (int ni=0;ni<4;ni++){
                int col = n0 + wn + ni*8 + 2*t4;
                float2 vv; vv.x = acc[mi][ni][half*2+0]; vv.y = acc[mi][ni][half*2+1];
                *(float2*)(cp + col) = vv;
            }
        }
    }
}

// split-K epilogues
__global__ __launch_bounds__(256) void add3e_k(float* __restrict__ x,
                                               const float* __restrict__ p,
                                               const float* __restrict__ bias,
                                               const float* __restrict__ posemb){
    int i = blockIdx.x*256 + threadIdx.x;
    if (i >= CBS*CD) return;
    int r = i / CD, d = i % CD;
    x[i] = p[i] + p[i + CXPART] + p[i + 2*CXPART] + bias[d]
         + posemb[(size_t)(r % CS)*CD + d];
}
__global__ __launch_bounds__(256) void add3r_k(float* __restrict__ x,
                                               const float* __restrict__ p,
                                               const float* __restrict__ bias){
    int i = blockIdx.x*256 + threadIdx.x;
    if (i >= CBS*CD) return;
    x[i] += p[i] + p[i + CXPART] + p[i + 2*CXPART] + bias[i % CD];
}

// =====================================================================
// w2 expert GEMM, split-K x4 (round 14 winner, unchanged)
// =====================================================================
__global__ __launch_bounds__(256,2) void tc_gemm_w2(
    const float* __restrict__ A,
    const float* __restrict__ Wl,    // [E][3072][768]
    float* __restrict__ C,           // 4 part images
    const int* __restrict__ counts)
{
    extern __shared__ float smf[];

    const int e = blockIdx.z;
    const int Me = counts[e];
    const int m0 = blockIdx.y*128;
    if (m0 >= Me) return;
    const int kp = blockIdx.x / 6;
    const int n0 = (blockIdx.x % 6)*128;
    const int tid = threadIdx.x, wid = tid>>5, lane = tid&31;
    const int wm = (wid>>2)*64;
    const int wn = (wid&3)*32;
    const int g = lane>>2, t4 = lane&3;

    const int rowA = tid>>1, segA = (tid&1)*16;
    const int rowB = tid>>3, segB = (tid&7)*16;

    const float* apBase = A + ((size_t)(e*CBSP + m0 + rowA))*CDF + kp*768 + segA;
    const float* bpBase = Wl + (size_t)e*CDF*CD + ((size_t)(kp*768 + rowB))*CD + n0 + segB;

    float acc[4][4][4];
    #pragma unroll
    for (int i=0;i<4;i++)
        #pragma unroll
        for (int j=0;j<4;j++)
            #pragma unroll
            for (int q=0;q<4;q++) acc[i][j][q] = 0.f;

    #pragma unroll
    for (int p=0; p<2; p++){
        float* As = smf + p*STG_FLOATS;
        float* Bs = As + SM_A;
        const float* ap = apBase + p*32;
        const float* bp = bpBase + (size_t)p*32*CD;
        #pragma unroll
        for (int i=0;i<4;i++) cp16(As + rowA*36 + segA + i*4, ap + i*4);
        #pragma unroll
        for (int i=0;i<4;i++) cp16(Bs + rowB*136 + segB + i*4, bp + i*4);
        CP_COMMIT();
    }

    for (int c = 0; c < 24; c++){
        CP_WAIT1();
        __syncthreads();
        const int st = c % 3;
        float* As = smf + st*STG_FLOATS;
        float* Bs = As + SM_A;

        if (c+2 < 24){
            const int st2 = (c+2) % 3;
            float* As2 = smf + st2*STG_FLOATS;
            float* Bs2 = As2 + SM_A;
            const float* ap = apBase + (c+2)*32;
            const float* bp = bpBase + (size_t)(c+2)*32*CD;
            #pragma unroll
            for (int i=0;i<4;i++) cp16(As2 + rowA*36 + segA + i*4, ap + i*4);
            #pragma unroll
            for (int i=0;i<4;i++) cp16(Bs2 + rowB*136 + segB + i*4, bp + i*4);
        }
        CP_COMMIT();

        #pragma unroll
        for (int ks=0; ks<4; ks++){
            unsigned ahr[4][4], alr[4][4];
            #pragma unroll
            for (int mi=0;mi<4;mi++){
                int r0 = (wm + mi*16 + g)*36 + ks*8 + t4;
                int r1 = r0 + 8*36;
                split1(As[r0],   ahr[mi][0], alr[mi][0]);
                split1(As[r1],   ahr[mi][1], alr[mi][1]);
                split1(As[r0+4], ahr[mi][2], alr[mi][2]);
                split1(As[r1+4], ahr[mi][3], alr[mi][3]);
            }
            #pragma unroll
            for (int ni=0;ni<4;ni++){
                int b0i = (ks*8 + t4)*136 + wn + ni*8 + g;
                int b1i = b0i + 4*136;
                unsigned bh0, bl0, bh1, bl1;
                split1(Bs[b0i], bh0, bl0);
                split1(Bs[b1i], bh1, bl1);
                #pragma unroll
                for (int mi=0;mi<4;mi++){
                    MMA_TF32(acc[mi][ni], ahr[mi][0],ahr[mi][1],ahr[mi][2],ahr[mi][3], bl0,bl1);
                    MMA_TF32(acc[mi][ni], alr[mi][0],alr[mi][1],alr[mi][2],alr[mi][3], bh0,bh1);
                    MMA_TF32(acc[mi][ni], ahr[mi][0],ahr[mi][1],ahr[mi][2],ahr[mi][3], bh0,bh1);
                }
            }
        }
    }

    float* Cp = C + (size_t)kp*CEPART;
    #pragma unroll
    for (int mi=0;mi<4;mi++){
        #pragma unroll
        for (int half=0; half<2; half++){
            int mm = m0 + wm + mi*16 + g + half*8;
            float* cp = Cp + ((size_t)(e*CBSP + mm))*CD;
            #pragma unroll
            for (int ni=0;ni<4;ni++){
                int col = n0 + wn + ni*8 + 2*t4;
                float2 vv; vv.x = acc[mi][ni][half*2+0]; vv.y = acc[mi][ni][half*2+1];
                *(float2*)(cp + col) = vv;
            }
        }
    }
}

// =====================================================================
// Tensor-core flash attention with cp.async double-buffered K/V
// =====================================================================
__global__ __launch_bounds__(128) void attn_tc(const float* __restrict__ qkv,
                                               const float* __restrict__ tb,
                                               float* __restrict__ out){
    extern __shared__ float sm[];
    float* Ps  = sm + ATT_PS;
    float* tbs = sm + ATT_TBS;

    const int h = blockIdx.y, b = blockIdx.z;
    const int q0 = blockIdx.x*64;
    const int tid = threadIdx.x, w = tid>>5, lane = tid&31;
    const int g = lane>>2, t4 = lane&3;
    const int wm = w*16;

    if (tid < 15) tbs[tid] = tb[h*15 + tid];

    const int row0 = q0 + wm + g, row1 = row0 + 8;
    const int r0c = row0 < CS ? row0 : CS-1;
    const int r1c = row1 < CS ? row1 : CS-1;
    const int fq0 = r0c / CN, fq1 = r1c / CN;

    unsigned qh[8][4], ql[8][4];
    {
        const float* q0p = qkv + (size_t)(b*CS + r0c)*C3D + h*64;
        const float* q1p = qkv + (size_t)(b*CS + r1c)*C3D + h*64;
        #pragma unroll
        for (int ks=0; ks<8; ks++){
            split1(q0p[ks*8+t4]  *0.125f, qh[ks][0], ql[ks][0]);
            split1(q1p[ks*8+t4]  *0.125f, qh[ks][1], ql[ks][1]);
            split1(q0p[ks*8+t4+4]*0.125f, qh[ks][2], ql[ks][2]);
            split1(q1p[ks*8+t4+4]*0.125f, qh[ks][3], ql[ks][3]);
        }
    }

    // prologue: issue chunk 0 into stage 0
    {
        float* Ks0 = sm + ATT_KS0;
        float* Vs0 = sm + ATT_VS0;
        for (int i = tid; i < 1024; i += 128){
            int j = i>>4, c4 = (i&15)*4;
            const float* kp_ = qkv + (size_t)(b*CS + j)*C3D + CD + h*64 + c4;
            cp16(Ks0 + j*68 + c4, kp_);
            cp16(Vs0 + j*72 + c4, kp_ + CD);
        }
        CP_COMMIT();
    }

    float o[8][4];
    #pragma unroll
    for (int ni=0;ni<8;ni++){ o[ni][0]=0.f; o[ni][1]=0.f; o[ni][2]=0.f; o[ni][3]=0.f; }
    float m0=-1e30f, m1=-1e30f, l0=0.f, l1=0.f;

    for (int kc = 0; kc < 25; kc++){
        CP_WAIT0();
        __syncthreads();   // chunk kc visible; all warps done reading other stage
        float* Ks = sm + ((kc&1) ? ATT_KS1 : ATT_KS0);
        float* Vs = sm + ((kc&1) ? ATT_VS1 : ATT_VS0);

        if (kc+1 < 25){
            float* Ks2 = sm + (((kc+1)&1) ? ATT_KS1 : ATT_KS0);
            float* Vs2 = sm + (((kc+1)&1) ? ATT_VS1 : ATT_VS0);
            for (int i = tid; i < 1024; i += 128){
                int j = i>>4, c4 = (i&15)*4;
                int key = (kc+1)*64 + j; if (key >= CS) key = CS-1;
                const float* kp_ = qkv + (size_t)(b*CS + key)*C3D + CD + h*64 + c4;
                cp16(Ks2 + j*68 + c4, kp_);
                cp16(Vs2 + j*72 + c4, kp_ + CD);
            }
        }
        CP_COMMIT();

        float s[8][4];
        #pragma unroll
        for (int ni=0;ni<8;ni++){ s[ni][0]=0.f; s[ni][1]=0.f; s[ni][2]=0.f; s[ni][3]=0.f; }
        #pragma unroll
        for (int ks=0; ks<8; ks++){
            #pragma unroll
            for (int ni=0; ni<8; ni++){
                int kb = (ni*8 + g)*68 + ks*8 + t4;
                unsigned bh0, bl0, bh1, bl1;
                split1(Ks[kb],   bh0, bl0);
                split1(Ks[kb+4], bh1, bl1);
                MMA_TF32(s[ni], qh[ks][0],qh[ks][1],qh[ks][2],qh[ks][3], bl0,bl1);
                MMA_TF32(s[ni], ql[ks][0],ql[ks][1],ql[ks][2],ql[ks][3], bh0,bh1);
                MMA_TF32(s[ni], qh[ks][0],qh[ks][1],qh[ks][2],qh[ks][3], bh0,bh1);
            }
        }

        float mx0=-1e30f, mx1=-1e30f;
        #pragma unroll
        for (int ni=0;ni<8;ni++){
            int k0 = kc*64 + ni*8 + 2*t4;
            if (k0 < CS){
                int fk = k0 / CN;
                s[ni][0] += tbs[fq0 - fk + 7];
                s[ni][2] += tbs[fq1 - fk + 7];
            } else { s[ni][0] = -1e30f; s[ni][2] = -1e30f; }
            if (k0+1 < CS){
                int fk = (k0+1) / CN;
                s[ni][1] += tbs[fq0 - fk + 7];
                s[ni][3] += tbs[fq1 - fk + 7];
            } else { s[ni][1] = -1e30f; s[ni][3] = -1e30f; }
            mx0 = fmaxf(mx0, fmaxf(s[ni][0], s[ni][1]));
            mx1 = fmaxf(mx1, fmaxf(s[ni][2], s[ni][3]));
        }
        mx0 = fmaxf(mx0, __shfl_xor_sync(0xffffffffu, mx0, 1));
        mx0 = fmaxf(mx0, __shfl_xor_sync(0xffffffffu, mx0, 2));
        mx1 = fmaxf(mx1, __shfl_xor_sync(0xffffffffu, mx1, 1));
        mx1 = fmaxf(mx1, __shfl_xor_sync(0xffffffffu, mx1, 2));

        float mn0 = fmaxf(m0, mx0), mn1 = fmaxf(m1, mx1);
        float c0 = __expf(m0 - mn0), c1 = __expf(m1 - mn1);
        float sp0 = 0.f, sp1 = 0.f;
        #pragma unroll
        for (int ni=0;ni<8;ni++){
            s[ni][0] = __expf(s[ni][0] - mn0);
            s[ni][1] = __expf(s[ni][1] - mn0);
            s[ni][2] = __expf(s[ni][2] - mn1);
            s[ni][3] = __expf(s[ni][3] - mn1);
            sp0 += s[ni][0] + s[ni][1];
            sp1 += s[ni][2] + s[ni][3];
            float2 p01; p01.x = s[ni][0]; p01.y = s[ni][1];
            float2 p23; p23.x = s[ni][2]; p23.y = s[ni][3];
            *(float2*)(Ps + (wm+g)*68   + ni*8 + 2*t4) = p01;
            *(float2*)(Ps + (wm+g+8)*68 + ni*8 + 2*t4) = p23;
        }
        sp0 += __shfl_xor_sync(0xffffffffu, sp0, 1);
        sp0 += __shfl_xor_sync(0xffffffffu, sp0, 2);
        sp1 += __shfl_xor_sync(0xffffffffu, sp1, 1);
        sp1 += __shfl_xor_sync(0xffffffffu, sp1, 2);
        l0 = l0*c0 + sp0;  l1 = l1*c1 + sp1;
        m0 = mn0; m1 = mn1;
        #pragma unroll
        for (int ni=0;ni<8;ni++){
            o[ni][0]*=c0; o[ni][1]*=c0; o[ni][2]*=c1; o[ni][3]*=c1;
        }
        __syncwarp();

        #pragma unroll
        for (int ks=0; ks<8; ks++){
            unsigned ah[4], al[4];
            int p0i = (wm+g)*68 + ks*8 + t4;
            int p1i = p0i + 8*68;
            split1(Ps[p0i],   ah[0], al[0]);
            split1(Ps[p1i],   ah[1], al[1]);
            split1(Ps[p0i+4], ah[2], al[2]);
            split1(Ps[p1i+4], ah[3], al[3]);
            #pragma unroll
            for (int ni=0; ni<8; ni++){
                int vb = (ks*8 + t4)*72 + ni*8 + g;
                unsigned bh0, bl0, bh1, bl1;
                split1(Vs[vb],      bh0, bl0);
                split1(Vs[vb+4*72], bh1, bl1);
                MMA_TF32(o[ni], ah[0],ah[1],ah[2],ah[3], bl0,bl1);
                MMA_TF32(o[ni], al[0],al[1],al[2],al[3], bh0,bh1);
                MMA_TF32(o[ni], ah[0],ah[1],ah[2],ah[3], bh0,bh1);
            }
        }
    }

    float inv0 = 1.f/l0, inv1 = 1.f/l1;
    if (row0 < CS){
        float* op = out + (size_t)(b*CS + row0)*CD + h*64;
        #pragma unroll
        for (int ni=0;ni<8;ni++){
            float2 vv; vv.x = o[ni][0]*inv0; vv.y = o[ni][1]*inv0;
            *(float2*)(op + ni*8 + 2*t4) = vv;
        }
    }
    if (row1 < CS){
        float* op = out + (size_t)(b*CS + row1)*CD + h*64;
        #pragma unroll
        for (int ni=0;ni<8;ni++){
            float2 vv; vv.x = o[ni][2]*inv1; vv.y = o[ni][3]*inv1;
            *(float2*)(op + ni*8 + 2*t4) = vv;
        }
    }
}

// ---------------- text projection (tiny) ----------------
__global__ __launch_bounds__(256) void textproj_k(const float* __restrict__ ts,
                                                  const float* __restrict__ wt,
                                                  const float* __restrict__ bt,
                                                  float* __restrict__ out){
    int i = blockIdx.x*256 + threadIdx.x;
    if (i >= CB*CD) return;
    int b = i/CD, d = i%CD;
    float a = bt[d];
    for (int k=0;k<CD;k++) a += ts[b*CD+k]*wt[(size_t)k*CD+d];
    out[i] = a;
}

__global__ void zero8_k(int* c){ if (threadIdx.x < CE) c[threadIdx.x] = 0; }

// ---------------- router ----------------
__global__ __launch_bounds__(256) void router_k(const float* __restrict__ h2,
                                                const float* __restrict__ tproj,
                                                const float* __restrict__ wr,
                                                int* __restrict__ counts,
                                                int* __restrict__ tok_of_slot,
                                                int* __restrict__ slot_of,
                                                float* __restrict__ gatev){
    int w = threadIdx.x >> 5, lane = threadIdx.x & 31;
    int r = blockIdx.x*8 + w;
    int b = r / CS;
    float acc[8] = {};
    for (int d = lane; d < CD; d += 32){
        float rv = h2[(size_t)r*CD + d] + tproj[b*CD + d];
        #pragma unroll
        for (int e=0;e<8;e++) acc[e] += rv * wr[d*8 + e];
    }
    #pragma unroll
    for (int e=0;e<8;e++)
        #pragma unroll
        for (int o=16;o;o>>=1) acc[e] += __shfl_xor_sync(0xffffffffu, acc[e], o);
    if (lane == 0){
        int i0 = 0; float v0 = acc[0];
        #pragma unroll
        for (int e=1;e<8;e++) if (acc[e] > v0){ v0=acc[e]; i0=e; }
        int i1 = -1; float v1 = -1e30f;
        #pragma unroll
        for (int e=0;e<8;e++) if (e!=i0 && acc[e] > v1){ v1=acc[e]; i1=e; }
        float g0 = 1.f/(1.f + expf(v1 - v0));
        float g1 = 1.f - g0;
        int p0 = atomicAdd(&counts[i0], 1);
        tok_of_slot[i0*CBS + p0] = r; slot_of[r*2]   = i0*CBSP + p0; gatev[r*2]   = g0;
        int p1 = atomicAdd(&counts[i1], 1);
        tok_of_slot[i1*CBS + p1] = r; slot_of[r*2+1] = i1*CBSP + p1; gatev[r*2+1] = g1;
    }
}

// ---------------- combine: sum 4 split-K part images + expert bias ----------------
__global__ __launch_bounds__(256) void combine4_k(float* __restrict__ x,
                                                  const float* __restrict__ moe,
                                                  const float* __restrict__ b2l,  // [E][CD]
                                                  const int* __restrict__ slot_of,
                                                  const float* __restrict__ gatev){
    int i = blockIdx.x*256 + threadIdx.x;
    if (i >= CBS*CD) return;
    int r = i / CD, d = i % CD;
    int sl0 = slot_of[r*2], sl1 = slot_of[r*2+1];
    size_t s0 = (size_t)sl0*CD + d;
    size_t s1 = (size_t)sl1*CD + d;
    float a0 = moe[s0] + moe[s0 + CEPART] + moe[s0 + 2*CEPART] + moe[s0 + 3*CEPART]
             + b2l[(sl0/CBSP)*CD + d];
    float a1 = moe[s1] + moe[s1 + CEPART] + moe[s1 + 2*CEPART] + moe[s1 + 3*CEPART]
             + b2l[(sl1/CBSP)*CD + d];
    x[i] = x[i] + gatev[r*2]*a0 + gatev[r*2+1]*a1;
}

// =============================== host ===============================
extern "C" void kernel_launch(void* const* d_in, const int* in_sizes, int n_in,
                              void* d_out, int out_size){
    const float* video   = (const float*)d_in[0];
    const float* text    = (const float*)d_in[1];
    const float* patch_w = (const float*)d_in[2];
    const float* patch_b = (const float*)d_in[3];
    const float* pos_emb = (const float*)d_in[4];
    const float* ln1s    = (const float*)d_in[5];
    const float* ln1b    = (const float*)d_in[6];
    const float* wqkv    = (const float*)d_in[7];
    const float* bqkv    = (const float*)d_in[8];
    const float* wo      = (const float*)d_in[9];
    const float* bo      = (const float*)d_in[10];
    const float* tbias   = (const float*)d_in[11];
    const float* ln2s    = (const float*)d_in[12];
    const float* ln2b    = (const float*)d_in[13];
    const float* wtext   = (const float*)d_in[14];
    const float* btext   = (const float*)d_in[15];
    const float* wrouter = (const float*)d_in[16];
    const float* w1      = (const float*)d_in[17];
    const float* b1      = (const float*)d_in[18];
    const float* w2      = (const float*)d_in[19];
    const float* b2      = (const float*)d_in[20];
    const float* lnfs    = (const float*)d_in[21];
    const float* lnfb    = (const float*)d_in[22];

    float *p_patches,*p_x,*p_h,*p_h2,*p_qkv,*p_att,*p_he,*p_moe4,*p_p3,*p_tproj,*p_gate;
    int *p_counts,*p_tok,*p_slot;
    cudaGetSymbolAddress((void**)&p_patches, g_patches);
    cudaGetSymbolAddress((void**)&p_x,       g_x);
    cudaGetSymbolAddress((void**)&p_h,       g_h);
    cudaGetSymbolAddress((void**)&p_h2,      g_h2);
    cudaGetSymbolAddress((void**)&p_qkv,     g_qkv);
    cudaGetSymbolAddress((void**)&p_att,     g_att);
    cudaGetSymbolAddress((void**)&p_he,      g_he);
    cudaGetSymbolAddress((void**)&p_moe4,    g_moe4);
    cudaGetSymbolAddress((void**)&p_p3,      g_p3);
    cudaGetSymbolAddress((void**)&p_tproj,   g_tproj);
    cudaGetSymbolAddress((void**)&p_counts,  g_counts);
    cudaGetSymbolAddress((void**)&p_tok,     g_tok);
    cudaGetSymbolAddress((void**)&p_slot,    g_slot);
    cudaGetSymbolAddress((void**)&p_gate,    g_gate);

    cudaFuncSetAttribute(tc_gemm, cudaFuncAttributeMaxDynamicSharedMemorySize, TC_SMEM_BYTES);
    cudaFuncSetAttribute(tc_gemm_sk3, cudaFuncAttributeMaxDynamicSharedMemorySize, TC_SMEM_BYTES);
    cudaFuncSetAttribute(tc_gemm_w2, cudaFuncAttributeMaxDynamicSharedMemorySize, TC_SMEM_BYTES);
    cudaFuncSetAttribute(attn_tc, cudaFuncAttributeMaxDynamicSharedMemorySize, ATT_SMEM_BYTES);

    const int EW = (CBS*CD + 255)/256;
    const int MB = (CBS + 127)/128;      // 25
    const int QB = (CS + 63)/64;         // 25

    // embed: split-K x3 -> p_p3, epilogue adds bias + pos_emb
    patchify_k<<<EW,256>>>(video, p_patches);
    tc_gemm_sk3<<<dim3(18, MB, 1),256,TC_SMEM_BYTES>>>(p_patches, patch_w, p_p3);
    add3e_k<<<EW,256>>>(p_x, p_p3, patch_b, pos_emb);

    for (int l = 0; l < 4; l++){
        // attention
        ln_k<<<CBS,256>>>(p_x, ln1s + l*CD, ln1b + l*CD, p_h);
        tc_gemm<<<dim3(C3D/128, MB, 1),256,TC_SMEM_BYTES>>>(
            CBS, C3D, CD, p_h, wqkv + (size_t)l*CD*C3D, 0, bqkv + l*C3D, 0,
            nullptr, nullptr, p_qkv, nullptr, nullptr, 0);
        attn_tc<<<dim3(QB, CHEADS, CB),128,ATT_SMEM_BYTES>>>(
            p_qkv, tbias + l*CHEADS*(2*CT-1), p_att);
        // WO: split-K x3 -> p_p3, epilogue adds bias + residual accumulate
        tc_gemm_sk3<<<dim3(18, MB, 1),256,TC_SMEM_BYTES>>>(
            p_att, wo + (size_t)l*CD*CD, p_p3);
        add3r_k<<<EW,256>>>(p_x, p_p3, bo + l*CD);
        // MoE
        ln_k<<<CBS,256>>>(p_x, ln2s + l*CD, ln2b + l*CD, p_h2);
        textproj_k<<<(CB*CD+255)/256,256>>>(text, wtext + (size_t)l*CD*CD, btext + l*CD, p_tproj);
        zero8_k<<<1,CE>>>(p_counts);
        router_k<<<CBS/8,256>>>(p_h2, p_tproj, wrouter + (size_t)l*CD*CE,
                                p_counts, p_tok, p_slot, p_gate);
        tc_gemm<<<dim3(CDF/128, MB, CE),256,TC_SMEM_BYTES>>>(
            CBS, CDF, CD, p_h2, w1 + (size_t)l*CE*CD*CDF, (size_t)CD*CDF,
            b1 + (size_t)l*CE*CDF, CDF,
            nullptr, nullptr, p_he, p_tok, p_counts, 1);
        tc_gemm_w2<<<dim3(4*6, MB, CE),256,TC_SMEM_BYTES>>>(
            p_he, w2 + (size_t)l*CE*CDF*CD, p_moe4, p_counts);
        combine4_k<<<EW,256>>>(p_x, p_moe4, b2 + (size_t)l*CE*CD, p_slot, p_gate);
    }

    ln_k<<<CBS,256>>>(p_x, lnfs, lnfb, (float*)d_out);
}

// round 16
// speedup vs baseline: 1.0115x; 1.0115x over previous
#include <cuda_runtime.h>
#include <math.h>

#define CB 2
#define CT 8
#define CHEADS 12
#define CD 768
#define CDF 3072
#define CE 8
#define CN 196
#define CS 1568
#define CBS 3136           // B*S
#define CBSP 3200          // padded per-expert row stride (25*128)
#define C3D 2304
#define CEPART ((size_t)CE*CBSP*CD)   // one k-part image of expert outputs
#define CXPART ((size_t)CBS*CD)       // one k-part image of dense outputs

// gemm smem per stage: raw A[128][36] + raw B[32][136]; THREE stages (cp.async ring)
#define SM_A  (128*36)
#define SM_B  (32*136)
#define STG_FLOATS (SM_A + SM_B)
#define TC_SMEM_BYTES (3*STG_FLOATS*4)

// attention smem (round-11 layout): Ks[64][68] + Vs[64][72] + Ps[64][68] + tbs
#define ATT_KS   0
#define ATT_VS   (64*68)
#define ATT_PS   (64*68 + 64*72)
#define ATT_TBS  (64*68 + 64*72 + 64*68)
#define ATT_SMEM_BYTES ((ATT_TBS + 16)*4)

// ---------------- scratch (device globals; no allocation allowed) ----------------
__device__ float g_patches[CBS*CD];
__device__ float g_x[CBS*CD];
__device__ float g_h[CBS*CD];
__device__ float g_h2[CBS*CD];
__device__ float g_qkv[CBS*C3D];
__device__ float g_att[CBS*CD];
__device__ float g_he[(size_t)CE*CBSP*CDF];   // expert hidden, slot-indexed (padded)
__device__ float g_moe4[4*CEPART];            // expert output, 4 split-K part images
__device__ float g_p3[3*CXPART];              // dense split-K partials (WO / embed)
__device__ float g_tproj[CB*CD];
__device__ int   g_counts[CE];
__device__ int   g_tok[CE*CBS];              // slot -> token row
__device__ int   g_slot[CBS*2];              // token -> its 2 slots (padded index)
__device__ float g_gate[CBS*2];              // token -> its 2 gates

__device__ __forceinline__ float gelu_t(float x){
    return 0.5f*x*(1.0f + tanhf(0.7978845608028654f*(x + 0.044715f*x*x*x)));
}

// mask-based tf32 hi/lo split
__device__ __forceinline__ void split1(float v, unsigned& h, unsigned& l){
    unsigned hu = __float_as_uint(v) & 0xFFFFE000u;
    h = hu;
    l = __float_as_uint(v - __uint_as_float(hu));
}

#define MMA_TF32(c, A0,A1,A2,A3, B0,B1) \
    asm volatile("mma.sync.aligned.m16n8k8.row.col.f32.tf32.tf32.f32 " \
        "{%0,%1,%2,%3}, {%4,%5,%6,%7}, {%8,%9}, {%0,%1,%2,%3};" \
        : "+f"((c)[0]),"+f"((c)[1]),"+f"((c)[2]),"+f"((c)[3]) \
        : "r"(A0),"r"(A1),"r"(A2),"r"(A3),"r"(B0),"r"(B1))

__device__ __forceinline__ void cp16(float* dst_smem, const float* src){
    unsigned d = (unsigned)__cvta_generic_to_shared(dst_smem);
    asm volatile("cp.async.cg.shared.global [%0], [%1], 16;" :: "r"(d), "l"(src));
}
#define CP_COMMIT() asm volatile("cp.async.commit_group;" ::: "memory")
#define CP_WAIT1()  asm volatile("cp.async.wait_group 1;" ::: "memory")

// ---------------- patchify ----------------
__global__ __launch_bounds__(256) void patchify_k(const float* __restrict__ video,
                                                  float* __restrict__ out){
    int i = blockIdx.x*256 + threadIdx.x;
    if (i >= CBS*CD) return;
    int r = i / CD, pp = i % CD;
    int b = r / CS, s = r % CS;
    int t = s / CN, pi = s % CN;
    int ph = pi / 14, pw = pi % 14;
    int c = pp >> 8, rem = pp & 255, py = rem >> 4, px = rem & 15;
    size_t vi = ((((size_t)b*CT + t)*3 + c)*224 + (ph*16+py))*224 + (pw*16+px);
    out[i] = video[vi];
}

// ---------------- fused LN helper (row-per-block; each thread owns 3 cols) ----
__device__ __forceinline__ void ln_row_store(float v0, float v1, float v2,
                                             const float* __restrict__ gs,
                                             const float* __restrict__ gb,
                                             float* __restrict__ orow, int d){
    float s = v0+v1+v2, sq = v0*v0+v1*v1+v2*v2;
    #pragma unroll
    for (int o=16;o;o>>=1){ s += __shfl_xor_sync(0xffffffffu,s,o); sq += __shfl_xor_sync(0xffffffffu,sq,o); }
    __shared__ float rs[8], rq[8];
    int w = threadIdx.x>>5;
    if ((threadIdx.x&31)==0){ rs[w]=s; rq[w]=sq; }
    __syncthreads();
    float ts=0.f, tq=0.f;
    #pragma unroll
    for (int i=0;i<8;i++){ ts+=rs[i]; tq+=rq[i]; }
    float mean = ts*(1.0f/CD);
    float var  = tq*(1.0f/CD) - mean*mean;
    float rstd = rsqrtf(var + 1e-5f);
    orow[d]     = (v0-mean)*rstd*gs[d]     + gb[d];
    orow[d+256] = (v1-mean)*rstd*gs[d+256] + gb[d+256];
    orow[d+512] = (v2-mean)*rstd*gs[d+512] + gb[d+512];
}

// embed epilogue: x = sum3(p) + bias + posemb;  h = LN(x)
__global__ __launch_bounds__(256) void add3e_ln_k(float* __restrict__ x,
                                                  const float* __restrict__ p,
                                                  const float* __restrict__ bias,
                                                  const float* __restrict__ posemb,
                                                  const float* __restrict__ gs,
                                                  const float* __restrict__ gb,
                                                  float* __restrict__ outp){
    int r = blockIdx.x, d = threadIdx.x;
    size_t base = (size_t)r*CD;
    const float* pe = posemb + (size_t)(r % CS)*CD;
    float v[3];
    #pragma unroll
    for (int j=0;j<3;j++){
        int dj = d + j*256;
        size_t i = base + dj;
        v[j] = p[i] + p[i + CXPART] + p[i + 2*CXPART] + bias[dj] + pe[dj];
        x[i] = v[j];
    }
    ln_row_store(v[0], v[1], v[2], gs, gb, outp + base, d);
}

// WO epilogue: x += sum3(p) + bias;  h2 = LN(x)
__global__ __launch_bounds__(256) void add3r_ln_k(float* __restrict__ x,
                                                  const float* __restrict__ p,
                                                  const float* __restrict__ bias,
                                                  const float* __restrict__ gs,
                                                  const float* __restrict__ gb,
                                                  float* __restrict__ outp){
    int r = blockIdx.x, d = threadIdx.x;
    size_t base = (size_t)r*CD;
    float v[3];
    #pragma unroll
    for (int j=0;j<3;j++){
        int dj = d + j*256;
        size_t i = base + dj;
        v[j] = x[i] + p[i] + p[i + CXPART] + p[i + 2*CXPART] + bias[dj];
        x[i] = v[j];
    }
    ln_row_store(v[0], v[1], v[2], gs, gb, outp + base, d);
}

// MoE epilogue: x += gates.(sum4 parts + expert bias);  outp = LN(x)
__global__ __launch_bounds__(256) void combine4_ln_k(float* __restrict__ x,
                                                     const float* __restrict__ moe,
                                                     const float* __restrict__ b2l,  // [E][CD]
                                                     const int* __restrict__ slot_of,
                                                     const float* __restrict__ gatev,
                                                     const float* __restrict__ gs,
                                                     const float* __restrict__ gb,
                                                     float* __restrict__ outp){
    int r = blockIdx.x, d = threadIdx.x;
    size_t base = (size_t)r*CD;
    int sl0 = slot_of[r*2], sl1 = slot_of[r*2+1];
    float g0 = gatev[r*2], g1 = gatev[r*2+1];
    const float* bb0 = b2l + (sl0/CBSP)*CD;
    const float* bb1 = b2l + (sl1/CBSP)*CD;
    float v[3];
    #pragma unroll
    for (int j=0;j<3;j++){
        int dj = d + j*256;
        size_t i = base + dj;
        size_t s0 = (size_t)sl0*CD + dj;
        size_t s1 = (size_t)sl1*CD + dj;
        float a0 = moe[s0] + moe[s0 + CEPART] + moe[s0 + 2*CEPART] + moe[s0 + 3*CEPART] + bb0[dj];
        float a1 = moe[s1] + moe[s1 + CEPART] + moe[s1 + 2*CEPART] + moe[s1 + 3*CEPART] + bb1[dj];
        v[j] = x[i] + g0*a0 + g1*a1;
        x[i] = v[j];
    }
    ln_row_store(v[0], v[1], v[2], gs, gb, outp + base, d);
}

// =====================================================================
// 3xTF32 mma.sync GEMM, cp.async 3-stage ring (round 13 winner, unchanged)
// =====================================================================
__global__ __launch_bounds__(256,2) void tc_gemm(
    int M, int N, int K,
    const float* __restrict__ A,
    const float* __restrict__ Wl, size_t wstride,
    const float* __restrict__ bl, int bstride,
    const float* __restrict__ addFull,
    const float* __restrict__ addRow,
    float* __restrict__ C,
    const int* __restrict__ tok,
    const int* __restrict__ counts,
    int doGelu)
{
    extern __shared__ float smf[];

    const int e = blockIdx.z;
    int Me = M;
    const float* W = Wl;
    const float* bias = bl;
    if (counts){
        Me = counts[e];
        W = Wl + (size_t)e*wstride;
        bias = bl + (size_t)e*bstride;
    }
    const int m0 = blockIdx.y*128;
    if (m0 >= Me) return;
    const int n0 = blockIdx.x*128;
    const int tid = threadIdx.x, wid = tid>>5, lane = tid&31;
    const int wm = (wid>>2)*64;
    const int wn = (wid&3)*32;
    const int g = lane>>2, t4 = lane&3;

    const int rowA = tid>>1, segA = (tid&1)*16;
    const int rowB = tid>>3, segB = (tid&7)*16;

    size_t arow;
    {
        int mm = m0 + rowA;
        if (tok)         arow = (size_t)tok[e*CBS + (mm < Me ? mm : 0)];
        else if (counts) arow = (size_t)e*CBSP + mm;
        else             arow = (size_t)(mm < M ? mm : (M-1));
    }
    const float* apBase = A + arow*(size_t)K + segA;
    const float* bpBase = W + (size_t)rowB*N + n0 + segB;

    float acc[4][4][4];
    #pragma unroll
    for (int i=0;i<4;i++)
        #pragma unroll
        for (int j=0;j<4;j++)
            #pragma unroll
            for (int q=0;q<4;q++) acc[i][j][q] = 0.f;

    const int nc = K/32;

    #pragma unroll
    for (int p=0; p<2; p++){
        float* As = smf + p*STG_FLOATS;
        float* Bs = As + SM_A;
        const float* ap = apBase + p*32;
        const float* bp = bpBase + (size_t)p*32*N;
        #pragma unroll
        for (int i=0;i<4;i++) cp16(As + rowA*36 + segA + i*4, ap + i*4);
        #pragma unroll
        for (int i=0;i<4;i++) cp16(Bs + rowB*136 + segB + i*4, bp + i*4);
        CP_COMMIT();
    }

    for (int c = 0; c < nc; c++){
        CP_WAIT1();
        __syncthreads();
        const int st = c % 3;
        float* As = smf + st*STG_FLOATS;
        float* Bs = As + SM_A;

        if (c+2 < nc){
            const int st2 = (c+2) % 3;
            float* As2 = smf + st2*STG_FLOATS;
            float* Bs2 = As2 + SM_A;
            const float* ap = apBase + (c+2)*32;
            const float* bp = bpBase + (size_t)(c+2)*32*N;
            #pragma unroll
            for (int i=0;i<4;i++) cp16(As2 + rowA*36 + segA + i*4, ap + i*4);
            #pragma unroll
            for (int i=0;i<4;i++) cp16(Bs2 + rowB*136 + segB + i*4, bp + i*4);
        }
        CP_COMMIT();

        #pragma unroll
        for (int ks=0; ks<4; ks++){
            unsigned ahr[4][4], alr[4][4];
            #pragma unroll
            for (int mi=0;mi<4;mi++){
                int r0 = (wm + mi*16 + g)*36 + ks*8 + t4;
                int r1 = r0 + 8*36;
                split1(As[r0],   ahr[mi][0], alr[mi][0]);
                split1(As[r1],   ahr[mi][1], alr[mi][1]);
                split1(As[r0+4], ahr[mi][2], alr[mi][2]);
                split1(As[r1+4], ahr[mi][3], alr[mi][3]);
            }
            #pragma unroll
            for (int ni=0;ni<4;ni++){
                int b0i = (ks*8 + t4)*136 + wn + ni*8 + g;
                int b1i = b0i + 4*136;
                unsigned bh0, bl0, bh1, bl1;
                split1(Bs[b0i], bh0, bl0);
                split1(Bs[b1i], bh1, bl1);
                #pragma unroll
                for (int mi=0;mi<4;mi++){
                    MMA_TF32(acc[mi][ni], ahr[mi][0],ahr[mi][1],ahr[mi][2],ahr[mi][3], bl0,bl1);
                    MMA_TF32(acc[mi][ni], alr[mi][0],alr[mi][1],alr[mi][2],alr[mi][3], bh0,bh1);
                    MMA_TF32(acc[mi][ni], ahr[mi][0],ahr[mi][1],ahr[mi][2],ahr[mi][3], bh0,bh1);
                }
            }
        }
    }

    #pragma unroll
    for (int mi=0;mi<4;mi++){
        #pragma unroll
        for (int half=0; half<2; half++){
            int mm = m0 + wm + mi*16 + g + half*8;
            if (!counts && mm >= M) continue;
            size_t crow = counts ? ((size_t)e*CBSP + mm) : (size_t)mm;
            float* cp = C + crow*N;
            const float* afp = addFull ? (addFull + crow*N) : (const float*)0;
            const float* arp = addRow  ? (addRow + (size_t)(mm % CS)*N) : (const float*)0;
            #pragma unroll
            for (int ni=0;ni<4;ni++){
                int col = n0 + wn + ni*8 + 2*t4;
                float v0 = acc[mi][ni][half*2+0] + bias[col];
                float v1 = acc[mi][ni][half*2+1] + bias[col+1];
                if (arp){ v0 += arp[col]; v1 += arp[col+1]; }
                if (afp){ v0 += afp[col]; v1 += afp[col+1]; }
                if (doGelu){ v0 = gelu_t(v0); v1 = gelu_t(v1); }
                float2 vv; vv.x = v0; vv.y = v1;
                *(float2*)(cp + col) = vv;
            }
        }
    }
}

// =====================================================================
// Dense split-K x3 GEMM, hardcoded N=768, K=768, Ksub=256 (8 chunks).
// =====================================================================
__global__ __launch_bounds__(256,2) void tc_gemm_sk3(
    const float* __restrict__ A,     // [CBS][768]
    const float* __restrict__ W,     // [768][768]
    float* __restrict__ C)           // 3 part images of [CBS][768]
{
    extern __shared__ float smf[];

    const int kp = blockIdx.x / 6;
    const int n0 = (blockIdx.x % 6)*128;
    const int m0 = blockIdx.y*128;
    const int tid = threadIdx.x, wid = tid>>5, lane = tid&31;
    const int wm = (wid>>2)*64;
    const int wn = (wid&3)*32;
    const int g = lane>>2, t4 = lane&3;

    const int rowA = tid>>1, segA = (tid&1)*16;
    const int rowB = tid>>3, segB = (tid&7)*16;

    int mmL = m0 + rowA; if (mmL >= CBS) mmL = CBS-1;
    const float* apBase = A + (size_t)mmL*CD + kp*256 + segA;
    const float* bpBase = W + (size_t)(kp*256 + rowB)*CD + n0 + segB;

    float acc[4][4][4];
    #pragma unroll
    for (int i=0;i<4;i++)
        #pragma unroll
        for (int j=0;j<4;j++)
            #pragma unroll
            for (int q=0;q<4;q++) acc[i][j][q] = 0.f;

    #pragma unroll
    for (int p=0; p<2; p++){
        float* As = smf + p*STG_FLOATS;
        float* Bs = As + SM_A;
        const float* ap = apBase + p*32;
        const float* bp = bpBase + (size_t)p*32*CD;
        #pragma unroll
        for (int i=0;i<4;i++) cp16(As + rowA*36 + segA + i*4, ap + i*4);
        #pragma unroll
        for (int i=0;i<4;i++) cp16(Bs + rowB*136 + segB + i*4, bp + i*4);
        CP_COMMIT();
    }

    for (int c = 0; c < 8; c++){
        CP_WAIT1();
        __syncthreads();
        const int st = c % 3;
        float* As = smf + st*STG_FLOATS;
        float* Bs = As + SM_A;

        if (c+2 < 8){
            const int st2 = (c+2) % 3;
            float* As2 = smf + st2*STG_FLOATS;
            float* Bs2 = As2 + SM_A;
            const float* ap = apBase + (c+2)*32;
            const float* bp = bpBase + (size_t)(c+2)*32*CD;
            #pragma unroll
            for (int i=0;i<4;i++) cp16(As2 + rowA*36 + segA + i*4, ap + i*4);
            #pragma unroll
            for (int i=0;i<4;i++) cp16(Bs2 + rowB*136 + segB + i*4, bp + i*4);
        }
        CP_COMMIT();

        #pragma unroll
        for (int ks=0; ks<4; ks++){
            unsigned ahr[4][4], alr[4][4];
            #pragma unroll
            for (int mi=0;mi<4;mi++){
                int r0 = (wm + mi*16 + g)*36 + ks*8 + t4;
                int r1 = r0 + 8*36;
                split1(As[r0],   ahr[mi][0], alr[mi][0]);
                split1(As[r1],   ahr[mi][1], alr[mi][1]);
                split1(As[r0+4], ahr[mi][2], alr[mi][2]);
                split1(As[r1+4], ahr[mi][3], alr[mi][3]);
            }
            #pragma unroll
            for (int ni=0;ni<4;ni++){
                int b0i = (ks*8 + t4)*136 + wn + ni*8 + g;
                int b1i = b0i + 4*136;
                unsigned bh0, bl0, bh1, bl1;
                split1(Bs[b0i], bh0, bl0);
                split1(Bs[b1i], bh1, bl1);
                #pragma unroll
                for (int mi=0;mi<4;mi++){
                    MMA_TF32(acc[mi][ni], ahr[mi][0],ahr[mi][1],ahr[mi][2],ahr[mi][3], bl0,bl1);
                    MMA_TF32(acc[mi][ni], alr[mi][0],alr[mi][1],alr[mi][2],alr[mi][3], bh0,bh1);
                    MMA_TF32(acc[mi][ni], ahr[mi][0],ahr[mi][1],ahr[mi][2],ahr[mi][3], bh0,bh1);
                }
            }
        }
    }

    float* Cp = C + (size_t)kp*CXPART;
    #pragma unroll
    for (int mi=0;mi<4;mi++){
        #pragma unroll
        for (int half=0; half<2; half++){
            int mm = m0 + wm + mi*16 + g + half*8;
            if (mm >= CBS) continue;
            float* cp = Cp + (size_t)mm*CD;
            #pragma unroll
            for (int ni=0;ni<4;ni++){
                int col = n0 + wn + ni*8 + 2*t4;
                float2 vv; vv.x = acc[mi][ni][half*2+0]; vv.y = acc[mi][ni][half*2+1];
                *(float2*)(cp + col) = vv;
            }
        }
    }
}

// =====================================================================
// w2 expert GEMM, split-K x4 (round 14 winner, unchanged)
// =====================================================================
__global__ __launch_bounds__(256,2) void tc_gemm_w2(
    const float* __restrict__ A,
    const float* __restrict__ Wl,    // [E][3072][768]
    float* __restrict__ C,           // 4 part images
    const int* __restrict__ counts)
{
    extern __shared__ float smf[];

    const int e = blockIdx.z;
    const int Me = counts[e];
    const int m0 = blockIdx.y*128;
    if (m0 >= Me) return;
    const int kp = blockIdx.x / 6;
    const int n0 = (blockIdx.x % 6)*128;
    const int tid = threadIdx.x, wid = tid>>5, lane = tid&31;
    const int wm = (wid>>2)*64;
    const int wn = (wid&3)*32;
    const int g = lane>>2, t4 = lane&3;

    const int rowA = tid>>1, segA = (tid&1)*16;
    const int rowB = tid>>3, segB = (tid&7)*16;

    const float* apBase = A + ((size_t)(e*CBSP + m0 + rowA))*CDF + kp*768 + segA;
    const float* bpBase = Wl + (size_t)e*CDF*CD + ((size_t)(kp*768 + rowB))*CD + n0 + segB;

    float acc[4][4][4];
    #pragma unroll
    for (int i=0;i<4;i++)
        #pragma unroll
        for (int j=0;j<4;j++)
            #pragma unroll
            for (int q=0;q<4;q++) acc[i][j][q] = 0.f;

    #pragma unroll
    for (int p=0; p<2; p++){
        float* As = smf + p*STG_FLOATS;
        float* Bs = As + SM_A;
        const float* ap = apBase + p*32;
        const float* bp = bpBase + (size_t)p*32*CD;
        #pragma unroll
        for (int i=0;i<4;i++) cp16(As + rowA*36 + segA + i*4, ap + i*4);
        #pragma unroll
        for (int i=0;i<4;i++) cp16(Bs + rowB*136 + segB + i*4, bp + i*4);
        CP_COMMIT();
    }

    for (int c = 0; c < 24; c++){
        CP_WAIT1();
        __syncthreads();
        const int st = c % 3;
        float* As = smf + st*STG_FLOATS;
        float* Bs = As + SM_A;

        if (c+2 < 24){
            const int st2 = (c+2) % 3;
            float* As2 = smf + st2*STG_FLOATS;
            float* Bs2 = As2 + SM_A;
            const float* ap = apBase + (c+2)*32;
            const float* bp = bpBase + (size_t)(c+2)*32*CD;
            #pragma unroll
            for (int i=0;i<4;i++) cp16(As2 + rowA*36 + segA + i*4, ap + i*4);
            #pragma unroll
            for (int i=0;i<4;i++) cp16(Bs2 + rowB*136 + segB + i*4, bp + i*4);
        }
        CP_COMMIT();

        #pragma unroll
        for (int ks=0; ks<4; ks++){
            unsigned ahr[4][4], alr[4][4];
            #pragma unroll
            for (int mi=0;mi<4;mi++){
                int r0 = (wm + mi*16 + g)*36 + ks*8 + t4;
                int r1 = r0 + 8*36;
                split1(As[r0],   ahr[mi][0], alr[mi][0]);
                split1(As[r1],   ahr[mi][1], alr[mi][1]);
                split1(As[r0+4], ahr[mi][2], alr[mi][2]);
                split1(As[r1+4], ahr[mi][3], alr[mi][3]);
            }
            #pragma unroll
            for (int ni=0;ni<4;ni++){
                int b0i = (ks*8 + t4)*136 + wn + ni*8 + g;
                int b1i = b0i + 4*136;
                unsigned bh0, bl0, bh1, bl1;
                split1(Bs[b0i], bh0, bl0);
                split1(Bs[b1i], bh1, bl1);
                #pragma unroll
                for (int mi=0;mi<4;mi++){
                    MMA_TF32(acc[mi][ni], ahr[mi][0],ahr[mi][1],ahr[mi][2],ahr[mi][3], bl0,bl1);
                    MMA_TF32(acc[mi][ni], alr[mi][0],alr[mi][1],alr[mi][2],alr[mi][3], bh0,bh1);
                    MMA_TF32(acc[mi][ni], ahr[mi][0],ahr[mi][1],ahr[mi][2],ahr[mi][3], bh0,bh1);
                }
            }
        }
    }

    float* Cp = C + (size_t)kp*CEPART;
    #pragma unroll
    for (int mi=0;mi<4;mi++){
        #pragma unroll
        for (int half=0; half<2; half++){
            int mm = m0 + wm + mi*16 + g + half*8;
            float* cp = Cp + ((size_t)(e*CBSP + mm))*CD;
            #pragma unroll
            for (int ni=0;ni<4;ni++){
                int col = n0 + wn + ni*8 + 2*t4;
                float2 vv; vv.x = acc[mi][ni][half*2+0]; vv.y = acc[mi][ni][half*2+1];
                *(float2*)(cp + col) = vv;
            }
        }
    }
}

// =====================================================================
// Tensor-core flash attention (round 11/14 winner, reverted to sync staging)
// =====================================================================
__global__ __launch_bounds__(128) void attn_tc(const float* __restrict__ qkv,
                                               const float* __restrict__ tb,
                                               float* __restrict__ out){
    extern __shared__ float sm[];
    float* Ks  = sm + ATT_KS;
    float* Vs  = sm + ATT_VS;
    float* Ps  = sm + ATT_PS;
    float* tbs = sm + ATT_TBS;

    const int h = blockIdx.y, b = blockIdx.z;
    const int q0 = blockIdx.x*64;
    const int tid = threadIdx.x, w = tid>>5, lane = tid&31;
    const int g = lane>>2, t4 = lane&3;
    const int wm = w*16;

    if (tid < 15) tbs[tid] = tb[h*15 + tid];

    const int row0 = q0 + wm + g, row1 = row0 + 8;
    const int r0c = row0 < CS ? row0 : CS-1;
    const int r1c = row1 < CS ? row1 : CS-1;
    const int fq0 = r0c / CN, fq1 = r1c / CN;

    unsigned qh[8][4], ql[8][4];
    {
        const float* q0p = qkv + (size_t)(b*CS + r0c)*C3D + h*64;
        const float* q1p = qkv + (size_t)(b*CS + r1c)*C3D + h*64;
        #pragma unroll
        for (int ks=0; ks<8; ks++){
            split1(q0p[ks*8+t4]  *0.125f, qh[ks][0], ql[ks][0]);
            split1(q1p[ks*8+t4]  *0.125f, qh[ks][1], ql[ks][1]);
            split1(q0p[ks*8+t4+4]*0.125f, qh[ks][2], ql[ks][2]);
            split1(q1p[ks*8+t4+4]*0.125f, qh[ks][3], ql[ks][3]);
        }
    }

    float o[8][4];
    #pragma unroll
    for (int ni=0;ni<8;ni++){ o[ni][0]=0.f; o[ni][1]=0.f; o[ni][2]=0.f; o[ni][3]=0.f; }
    float m0=-1e30f, m1=-1e30f, l0=0.f, l1=0.f;

    for (int kc = 0; kc < 25; kc++){
        __syncthreads();
        for (int i = tid; i < 1024; i += 128){
            int j = i>>4, c4 = (i&15)*4;
            int key = kc*64 + j; if (key >= CS) key = CS-1;
            const float* kp = qkv + (size_t)(b*CS + key)*C3D + CD + h*64 + c4;
            *(float4*)(Ks + j*68 + c4) = *(const float4*)kp;
            *(float4*)(Vs + j*72 + c4) = *(const float4*)(kp + CD);
        }
        __syncthreads();

        float s[8][4];
        #pragma unroll
        for (int ni=0;ni<8;ni++){ s[ni][0]=0.f; s[ni][1]=0.f; s[ni][2]=0.f; s[ni][3]=0.f; }
        #pragma unroll
        for (int ks=0; ks<8; ks++){
            #pragma unroll
            for (int ni=0; ni<8; ni++){
                int kb = (ni*8 + g)*68 + ks*8 + t4;
                unsigned bh0, bl0, bh1, bl1;
                split1(Ks[kb],   bh0, bl0);
                split1(Ks[kb+4], bh1, bl1);
                MMA_TF32(s[ni], qh[ks][0],qh[ks][1],qh[ks][2],qh[ks][3], bl0,bl1);
                MMA_TF32(s[ni], ql[ks][0],ql[ks][1],ql[ks][2],ql[ks][3], bh0,bh1);
                MMA_TF32(s[ni], qh[ks][0],qh[ks][1],qh[ks][2],qh[ks][3], bh0,bh1);
            }
        }

        float mx0=-1e30f, mx1=-1e30f;
        #pragma unroll
        for (int ni=0;ni<8;ni++){
            int k0 = kc*64 + ni*8 + 2*t4;
            if (k0 < CS){
                int fk = k0 / CN;
                s[ni][0] += tbs[fq0 - fk + 7];
                s[ni][2] += tbs[fq1 - fk + 7];
            } else { s[ni][0] = -1e30f; s[ni][2] = -1e30f; }
            if (k0+1 < CS){
                int fk = (k0+1) / CN;
                s[ni][1] += tbs[fq0 - fk + 7];
                s[ni][3] += tbs[fq1 - fk + 7];
            } else { s[ni][1] = -1e30f; s[ni][3] = -1e30f; }
            mx0 = fmaxf(mx0, fmaxf(s[ni][0], s[ni][1]));
            mx1 = fmaxf(mx1, fmaxf(s[ni][2], s[ni][3]));
        }
        mx0 = fmaxf(mx0, __shfl_xor_sync(0xffffffffu, mx0, 1));
        mx0 = fmaxf(mx0, __shfl_xor_sync(0xffffffffu, mx0, 2));
        mx1 = fmaxf(mx1, __shfl_xor_sync(0xffffffffu, mx1, 1));
        mx1 = fmaxf(mx1, __shfl_xor_sync(0xffffffffu, mx1, 2));

        float mn0 = fmaxf(m0, mx0), mn1 = fmaxf(m1, mx1);
        float c0 = __expf(m0 - mn0), c1 = __expf(m1 - mn1);
        float sp0 = 0.f, sp1 = 0.f;
        #pragma unroll
        for (int ni=0;ni<8;ni++){
            s[ni][0] = __expf(s[ni][0] - mn0);
            s[ni][1] = __expf(s[ni][1] - mn0);
            s[ni][2] = __expf(s[ni][2] - mn1);
            s[ni][3] = __expf(s[ni][3] - mn1);
            sp0 += s[ni][0] + s[ni][1];
            sp1 += s[ni][2] + s[ni][3];
            float2 p01; p01.x = s[ni][0]; p01.y = s[ni][1];
            float2 p23; p23.x = s[ni][2]; p23.y = s[ni][3];
            *(float2*)(Ps + (wm+g)*68   + ni*8 + 2*t4) = p01;
            *(float2*)(Ps + (wm+g+8)*68 + ni*8 + 2*t4) = p23;
        }
        sp0 += __shfl_xor_sync(0xffffffffu, sp0, 1);
        sp0 += __shfl_xor_sync(0xffffffffu, sp0, 2);
        sp1 += __shfl_xor_sync(0xffffffffu, sp1, 1);
        sp1 += __shfl_xor_sync(0xffffffffu, sp1, 2);
        l0 = l0*c0 + sp0;  l1 = l1*c1 + sp1;
        m0 = mn0; m1 = mn1;
        #pragma unroll
        for (int ni=0;ni<8;ni++){
            o[ni][0]*=c0; o[ni][1]*=c0; o[ni][2]*=c1; o[ni][3]*=c1;
        }
        __syncwarp();

        #pragma unroll
        for (int ks=0; ks<8; ks++){
            unsigned ah[4], al[4];
            int p0i = (wm+g)*68 + ks*8 + t4;
            int p1i = p0i + 8*68;
            split1(Ps[p0i],   ah[0], al[0]);
            split1(Ps[p1i],   ah[1], al[1]);
            split1(Ps[p0i+4], ah[2], al[2]);
            split1(Ps[p1i+4], ah[3], al[3]);
            #pragma unroll
            for (int ni=0; ni<8; ni++){
                int vb = (ks*8 + t4)*72 + ni*8 + g;
                unsigned bh0, bl0, bh1, bl1;
                split1(Vs[vb],      bh0, bl0);
                split1(Vs[vb+4*72], bh1, bl1);
                MMA_TF32(o[ni], ah[0],ah[1],ah[2],ah[3], bl0,bl1);
                MMA_TF32(o[ni], al[0],al[1],al[2],al[3], bh0,bh1);
                MMA_TF32(o[ni], ah[0],ah[1],ah[2],ah[3], bh0,bh1);
            }
        }
    }

    float inv0 = 1.f/l0, inv1 = 1.f/l1;
    if (row0 < CS){
        float* op = out + (size_t)(b*CS + row0)*CD + h*64;
        #pragma unroll
        for (int ni=0;ni<8;ni++){
            float2 vv; vv.x = o[ni][0]*inv0; vv.y = o[ni][1]*inv0;
            *(float2*)(op + ni*8 + 2*t4) = vv;
        }
    }
    if (row1 < CS){
        float* op = out + (size_t)(b*CS + row1)*CD + h*64;
        #pragma unroll
        for (int ni=0;ni<8;ni++){
            float2 vv; vv.x = o[ni][2]*inv1; vv.y = o[ni][3]*inv1;
            *(float2*)(op + ni*8 + 2*t4) = vv;
        }
    }
}

// ---------------- text projection (tiny) ----------------
__global__ __launch_bounds__(256) void textproj_k(const float* __restrict__ ts,
                                                  const float* __restrict__ wt,
                                                  const float* __restrict__ bt,
                                                  float* __restrict__ out){
    int i = blockIdx.x*256 + threadIdx.x;
    if (i >= CB*CD) return;
    int b = i/CD, d = i%CD;
    float a = bt[d];
    for (int k=0;k<CD;k++) a += ts[b*CD+k]*wt[(size_t)k*CD+d];
    out[i] = a;
}

__global__ void zero8_k(int* c){ if (threadIdx.x < CE) c[threadIdx.x] = 0; }

// ---------------- router ----------------
__global__ __launch_bounds__(256) void router_k(const float* __restrict__ h2,
                                                const float* __restrict__ tproj,
                                                const float* __restrict__ wr,
                                                int* __restrict__ counts,
                                                int* __restrict__ tok_of_slot,
                                                int* __restrict__ slot_of,
                                                float* __restrict__ gatev){
    int w = threadIdx.x >> 5, lane = threadIdx.x & 31;
    int r = blockIdx.x*8 + w;
    int b = r / CS;
    float acc[8] = {};
    for (int d = lane; d < CD; d += 32){
        float rv = h2[(size_t)r*CD + d] + tproj[b*CD + d];
        #pragma unroll
        for (int e=0;e<8;e++) acc[e] += rv * wr[d*8 + e];
    }
    #pragma unroll
    for (int e=0;e<8;e++)
        #pragma unroll
        for (int o=16;o;o>>=1) acc[e] += __shfl_xor_sync(0xffffffffu, acc[e], o);
    if (lane == 0){
        int i0 = 0; float v0 = acc[0];
        #pragma unroll
        for (int e=1;e<8;e++) if (acc[e] > v0){ v0=acc[e]; i0=e; }
        int i1 = -1; float v1 = -1e30f;
        #pragma unroll
        for (int e=0;e<8;e++) if (e!=i0 && acc[e] > v1){ v1=acc[e]; i1=e; }
        float g0 = 1.f/(1.f + expf(v1 - v0));
        float g1 = 1.f - g0;
        int p0 = atomicAdd(&counts[i0], 1);
        tok_of_slot[i0*CBS + p0] = r; slot_of[r*2]   = i0*CBSP + p0; gatev[r*2]   = g0;
        int p1 = atomicAdd(&counts[i1], 1);
        tok_of_slot[i1*CBS + p1] = r; slot_of[r*2+1] = i1*CBSP + p1; gatev[r*2+1] = g1;
    }
}

// =============================== host ===============================
extern "C" void kernel_launch(void* const* d_in, const int* in_sizes, int n_in,
                              void* d_out, int out_size){
    const float* video   = (const float*)d_in[0];
    const float* text    = (const float*)d_in[1];
    const float* patch_w = (const float*)d_in[2];
    const float* patch_b = (const float*)d_in[3];
    const float* pos_emb = (const float*)d_in[4];
    const float* ln1s    = (const float*)d_in[5];
    const float* ln1b    = (const float*)d_in[6];
    const float* wqkv    = (const float*)d_in[7];
    const float* bqkv    = (const float*)d_in[8];
    const float* wo      = (const float*)d_in[9];
    const float* bo      = (const float*)d_in[10];
    const float* tbias   = (const float*)d_in[11];
    const float* ln2s    = (const float*)d_in[12];
    const float* ln2b    = (const float*)d_in[13];
    const float* wtext   = (const float*)d_in[14];
    const float* btext   = (const float*)d_in[15];
    const float* wrouter = (const float*)d_in[16];
    const float* w1      = (const float*)d_in[17];
    const float* b1      = (const float*)d_in[18];
    const float* w2      = (const float*)d_in[19];
    const float* b2      = (const float*)d_in[20];
    const float* lnfs    = (const float*)d_in[21];
    const float* lnfb    = (const float*)d_in[22];

    float *p_patches,*p_x,*p_h,*p_h2,*p_qkv,*p_att,*p_he,*p_moe4,*p_p3,*p_tproj,*p_gate;
    int *p_counts,*p_tok,*p_slot;
    cudaGetSymbolAddress((void**)&p_patches, g_patches);
    cudaGetSymbolAddress((void**)&p_x,       g_x);
    cudaGetSymbolAddress((void**)&p_h,       g_h);
    cudaGetSymbolAddress((void**)&p_h2,      g_h2);
    cudaGetSymbolAddress((void**)&p_qkv,     g_qkv);
    cudaGetSymbolAddress((void**)&p_att,     g_att);
    cudaGetSymbolAddress((void**)&p_he,      g_he);
    cudaGetSymbolAddress((void**)&p_moe4,    g_moe4);
    cudaGetSymbolAddress((void**)&p_p3,      g_p3);
    cudaGetSymbolAddress((void**)&p_tproj,   g_tproj);
    cudaGetSymbolAddress((void**)&p_counts,  g_counts);
    cudaGetSymbolAddress((void**)&p_tok,     g_tok);
    cudaGetSymbolAddress((void**)&p_slot,    g_slot);
    cudaGetSymbolAddress((void**)&p_gate,    g_gate);

    cudaFuncSetAttribute(tc_gemm, cudaFuncAttributeMaxDynamicSharedMemorySize, TC_SMEM_BYTES);
    cudaFuncSetAttribute(tc_gemm_sk3, cudaFuncAttributeMaxDynamicSharedMemorySize, TC_SMEM_BYTES);
    cudaFuncSetAttribute(tc_gemm_w2, cudaFuncAttributeMaxDynamicSharedMemorySize, TC_SMEM_BYTES);
    cudaFuncSetAttribute(attn_tc, cudaFuncAttributeMaxDynamicSharedMemorySize, ATT_SMEM_BYTES);

    const int EW = (CBS*CD + 255)/256;
    const int MB = (CBS + 127)/128;      // 25
    const int QB = (CS + 63)/64;         // 25

    // embed: split-K x3 -> p_p3; fused epilogue: x = sum+bias+pos, h = LN1_0(x)
    patchify_k<<<EW,256>>>(video, p_patches);
    tc_gemm_sk3<<<dim3(18, MB, 1),256,TC_SMEM_BYTES>>>(p_patches, patch_w, p_p3);
    add3e_ln_k<<<CBS,256>>>(p_x, p_p3, patch_b, pos_emb, ln1s, ln1b, p_h);

    for (int l = 0; l < 4; l++){
        // attention
        tc_gemm<<<dim3(C3D/128, MB, 1),256,TC_SMEM_BYTES>>>(
            CBS, C3D, CD, p_h, wqkv + (size_t)l*CD*C3D, 0, bqkv + l*C3D, 0,
            nullptr, nullptr, p_qkv, nullptr, nullptr, 0);
        attn_tc<<<dim3(QB, CHEADS, CB),128,ATT_SMEM_BYTES>>>(
            p_qkv, tbias + l*CHEADS*(2*CT-1), p_att);
        // WO: split-K x3; fused epilogue: x += sum+bias, h2 = LN2_l(x)
        tc_gemm_sk3<<<dim3(18, MB, 1),256,TC_SMEM_BYTES>>>(
            p_att, wo + (size_t)l*CD*CD, p_p3);
        add3r_ln_k<<<CBS,256>>>(p_x, p_p3, bo + l*CD, ln2s + l*CD, ln2b + l*CD, p_h2);
        // MoE
        textproj_k<<<(CB*CD+255)/256,256>>>(text, wtext + (size_t)l*CD*CD, btext + l*CD, p_tproj);
        zero8_k<<<1,CE>>>(p_counts);
        router_k<<<CBS/8,256>>>(p_h2, p_tproj, wrouter + (size_t)l*CD*CE,
                                p_counts, p_tok, p_slot, p_gate);
        tc_gemm<<<dim3(CDF/128, MB, CE),256,TC_SMEM_BYTES>>>(
            CBS, CDF, CD, p_h2, w1 + (size_t)l*CE*CD*CDF, (size_t)CD*CDF,
            b1 + (size_t)l*CE*CDF, CDF,
            nullptr, nullptr, p_he, p_tok, p_counts, 1);
        tc_gemm_w2<<<dim3(4*6, MB, CE),256,TC_SMEM_BYTES>>>(
            p_he, w2 + (size_t)l*CE*CDF*CD, p_moe4, p_counts);
        // fused combine + next LN (lnf on last layer, writing d_out)
        if (l < 3){
            combine4_ln_k<<<CBS,256>>>(p_x, p_moe4, b2 + (size_t)l*CE*CD, p_slot, p_gate,
                                       ln1s + (l+1)*CD, ln1b + (l+1)*CD, p_h);
        } else {
            combine4_ln_k<<<CBS,256>>>(p_x, p_moe4, b2 + (size_t)l*CE*CD, p_slot, p_gate,
                                       lnfs, lnfb, (float*)d_out);
        }
    }
}

// round 17
// speedup vs baseline: 1.0169x; 1.0054x over previous
#include <cuda_runtime.h>
#include <math.h>

#define CB 2
#define CT 8
#define CHEADS 12
#define CD 768
#define CDF 3072
#define CE 8
#define CN 196
#define CS 1568
#define CBS 3136           // B*S
#define CBSP 3200          // padded per-expert row stride (25*128)
#define C3D 2304
#define CEPART ((size_t)CE*CBSP*CD)   // one k-part image of expert outputs
#define CXPART ((size_t)CBS*CD)       // one k-part image of dense outputs

// gemm smem per stage: raw A[128][36] + raw B[32][136]; THREE stages (cp.async ring)
#define SM_A  (128*36)
#define SM_B  (32*136)
#define STG_FLOATS (SM_A + SM_B)
#define TC_SMEM_BYTES (3*STG_FLOATS*4)

// attention smem: double-buffered 32-key stages + P + bias
// Ks[2][32][68], Vs[2][32][72], Ps[64][36], tbs
#define ATT_KS0  0
#define ATT_KS1  (32*68)
#define ATT_VS0  (2*32*68)
#define ATT_VS1  (2*32*68 + 32*72)
#define ATT_PS   (2*32*68 + 2*32*72)
#define ATT_TBS  (2*32*68 + 2*32*72 + 64*36)
#define ATT_SMEM_BYTES ((ATT_TBS + 16)*4)

// ---------------- scratch (device globals; no allocation allowed) ----------------
__device__ float g_patches[CBS*CD];
__device__ float g_x[CBS*CD];
__device__ float g_h[CBS*CD];
__device__ float g_h2[CBS*CD];
__device__ float g_qkv[CBS*C3D];
__device__ float g_att[CBS*CD];
__device__ float g_he[(size_t)CE*CBSP*CDF];   // expert hidden, slot-indexed (padded)
__device__ float g_moe4[4*CEPART];            // expert output, 4 split-K part images
__device__ float g_p3[3*CXPART];              // dense split-K partials (WO / embed)
__device__ float g_tproj[CB*CD];
__device__ int   g_counts[CE];
__device__ int   g_tok[CE*CBS];              // slot -> token row
__device__ int   g_slot[CBS*2];              // token -> its 2 slots (padded index)
__device__ float g_gate[CBS*2];              // token -> its 2 gates

__device__ __forceinline__ float gelu_t(float x){
    return 0.5f*x*(1.0f + tanhf(0.7978845608028654f*(x + 0.044715f*x*x*x)));
}

// mask-based tf32 hi/lo split
__device__ __forceinline__ void split1(float v, unsigned& h, unsigned& l){
    unsigned hu = __float_as_uint(v) & 0xFFFFE000u;
    h = hu;
    l = __float_as_uint(v - __uint_as_float(hu));
}

#define MMA_TF32(c, A0,A1,A2,A3, B0,B1) \
    asm volatile("mma.sync.aligned.m16n8k8.row.col.f32.tf32.tf32.f32 " \
        "{%0,%1,%2,%3}, {%4,%5,%6,%7}, {%8,%9}, {%0,%1,%2,%3};" \
        : "+f"((c)[0]),"+f"((c)[1]),"+f"((c)[2]),"+f"((c)[3]) \
        : "r"(A0),"r"(A1),"r"(A2),"r"(A3),"r"(B0),"r"(B1))

__device__ __forceinline__ void cp16(float* dst_smem, const float* src){
    unsigned d = (unsigned)__cvta_generic_to_shared(dst_smem);
    asm volatile("cp.async.cg.shared.global [%0], [%1], 16;" :: "r"(d), "l"(src));
}
#define CP_COMMIT() asm volatile("cp.async.commit_group;" ::: "memory")
#define CP_WAIT1()  asm volatile("cp.async.wait_group 1;" ::: "memory")
#define CP_WAIT0()  asm volatile("cp.async.wait_group 0;" ::: "memory")

// ---------------- patchify ----------------
__global__ __launch_bounds__(256) void patchify_k(const float* __restrict__ video,
                                                  float* __restrict__ out){
    int i = blockIdx.x*256 + threadIdx.x;
    if (i >= CBS*CD) return;
    int r = i / CD, pp = i % CD;
    int b = r / CS, s = r % CS;
    int t = s / CN, pi = s % CN;
    int ph = pi / 14, pw = pi % 14;
    int c = pp >> 8, rem = pp & 255, py = rem >> 4, px = rem & 15;
    size_t vi = ((((size_t)b*CT + t)*3 + c)*224 + (ph*16+py))*224 + (pw*16+px);
    out[i] = video[vi];
}

// ---------------- fused LN helper (row-per-block; each thread owns 3 cols) ----
__device__ __forceinline__ void ln_row_store(float v0, float v1, float v2,
                                             const float* __restrict__ gs,
                                             const float* __restrict__ gb,
                                             float* __restrict__ orow, int d){
    float s = v0+v1+v2, sq = v0*v0+v1*v1+v2*v2;
    #pragma unroll
    for (int o=16;o;o>>=1){ s += __shfl_xor_sync(0xffffffffu,s,o); sq += __shfl_xor_sync(0xffffffffu,sq,o); }
    __shared__ float rs[8], rq[8];
    int w = threadIdx.x>>5;
    if ((threadIdx.x&31)==0){ rs[w]=s; rq[w]=sq; }
    __syncthreads();
    float ts=0.f, tq=0.f;
    #pragma unroll
    for (int i=0;i<8;i++){ ts+=rs[i]; tq+=rq[i]; }
    float mean = ts*(1.0f/CD);
    float var  = tq*(1.0f/CD) - mean*mean;
    float rstd = rsqrtf(var + 1e-5f);
    orow[d]     = (v0-mean)*rstd*gs[d]     + gb[d];
    orow[d+256] = (v1-mean)*rstd*gs[d+256] + gb[d+256];
    orow[d+512] = (v2-mean)*rstd*gs[d+512] + gb[d+512];
}

// embed epilogue: x = sum3(p) + bias + posemb;  h = LN(x)
__global__ __launch_bounds__(256) void add3e_ln_k(float* __restrict__ x,
                                                  const float* __restrict__ p,
                                                  const float* __restrict__ bias,
                                                  const float* __restrict__ posemb,
                                                  const float* __restrict__ gs,
                                                  const float* __restrict__ gb,
                                                  float* __restrict__ outp){
    int r = blockIdx.x, d = threadIdx.x;
    size_t base = (size_t)r*CD;
    const float* pe = posemb + (size_t)(r % CS)*CD;
    float v[3];
    #pragma unroll
    for (int j=0;j<3;j++){
        int dj = d + j*256;
        size_t i = base + dj;
        v[j] = p[i] + p[i + CXPART] + p[i + 2*CXPART] + bias[dj] + pe[dj];
        x[i] = v[j];
    }
    ln_row_store(v[0], v[1], v[2], gs, gb, outp + base, d);
}

// WO epilogue: x += sum3(p) + bias;  h2 = LN(x)
__global__ __launch_bounds__(256) void add3r_ln_k(float* __restrict__ x,
                                                  const float* __restrict__ p,
                                                  const float* __restrict__ bias,
                                                  const float* __restrict__ gs,
                                                  const float* __restrict__ gb,
                                                  float* __restrict__ outp){
    int r = blockIdx.x, d = threadIdx.x;
    size_t base = (size_t)r*CD;
    float v[3];
    #pragma unroll
    for (int j=0;j<3;j++){
        int dj = d + j*256;
        size_t i = base + dj;
        v[j] = x[i] + p[i] + p[i + CXPART] + p[i + 2*CXPART] + bias[dj];
        x[i] = v[j];
    }
    ln_row_store(v[0], v[1], v[2], gs, gb, outp + base, d);
}

// MoE epilogue: x += gates.(sum4 parts + expert bias);  outp = LN(x)
__global__ __launch_bounds__(256) void combine4_ln_k(float* __restrict__ x,
                                                     const float* __restrict__ moe,
                                                     const float* __restrict__ b2l,  // [E][CD]
                                                     const int* __restrict__ slot_of,
                                                     const float* __restrict__ gatev,
                                                     const float* __restrict__ gs,
                                                     const float* __restrict__ gb,
                                                     float* __restrict__ outp){
    int r = blockIdx.x, d = threadIdx.x;
    size_t base = (size_t)r*CD;
    int sl0 = slot_of[r*2], sl1 = slot_of[r*2+1];
    float g0 = gatev[r*2], g1 = gatev[r*2+1];
    const float* bb0 = b2l + (sl0/CBSP)*CD;
    const float* bb1 = b2l + (sl1/CBSP)*CD;
    float v[3];
    #pragma unroll
    for (int j=0;j<3;j++){
        int dj = d + j*256;
        size_t i = base + dj;
        size_t s0 = (size_t)sl0*CD + dj;
        size_t s1 = (size_t)sl1*CD + dj;
        float a0 = moe[s0] + moe[s0 + CEPART] + moe[s0 + 2*CEPART] + moe[s0 + 3*CEPART] + bb0[dj];
        float a1 = moe[s1] + moe[s1 + CEPART] + moe[s1 + 2*CEPART] + moe[s1 + 3*CEPART] + bb1[dj];
        v[j] = x[i] + g0*a0 + g1*a1;
        x[i] = v[j];
    }
    ln_row_store(v[0], v[1], v[2], gs, gb, outp + base, d);
}

// =====================================================================
// 3xTF32 mma.sync GEMM, cp.async 3-stage ring (round 13 winner, unchanged)
// =====================================================================
__global__ __launch_bounds__(256,2) void tc_gemm(
    int M, int N, int K,
    const float* __restrict__ A,
    const float* __restrict__ Wl, size_t wstride,
    const float* __restrict__ bl, int bstride,
    const float* __restrict__ addFull,
    const float* __restrict__ addRow,
    float* __restrict__ C,
    const int* __restrict__ tok,
    const int* __restrict__ counts,
    int doGelu)
{
    extern __shared__ float smf[];

    const int e = blockIdx.z;
    int Me = M;
    const float* W = Wl;
    const float* bias = bl;
    if (counts){
        Me = counts[e];
        W = Wl + (size_t)e*wstride;
        bias = bl + (size_t)e*bstride;
    }
    const int m0 = blockIdx.y*128;
    if (m0 >= Me) return;
    const int n0 = blockIdx.x*128;
    const int tid = threadIdx.x, wid = tid>>5, lane = tid&31;
    const int wm = (wid>>2)*64;
    const int wn = (wid&3)*32;
    const int g = lane>>2, t4 = lane&3;

    const int rowA = tid>>1, segA = (tid&1)*16;
    const int rowB = tid>>3, segB = (tid&7)*16;

    size_t arow;
    {
        int mm = m0 + rowA;
        if (tok)         arow = (size_t)tok[e*CBS + (mm < Me ? mm : 0)];
        else if (counts) arow = (size_t)e*CBSP + mm;
        else             arow = (size_t)(mm < M ? mm : (M-1));
    }
    const float* apBase = A + arow*(size_t)K + segA;
    const float* bpBase = W + (size_t)rowB*N + n0 + segB;

    float acc[4][4][4];
    #pragma unroll
    for (int i=0;i<4;i++)
        #pragma unroll
        for (int j=0;j<4;j++)
            #pragma unroll
            for (int q=0;q<4;q++) acc[i][j][q] = 0.f;

    const int nc = K/32;

    #pragma unroll
    for (int p=0; p<2; p++){
        float* As = smf + p*STG_FLOATS;
        float* Bs = As + SM_A;
        const float* ap = apBase + p*32;
        const float* bp = bpBase + (size_t)p*32*N;
        #pragma unroll
        for (int i=0;i<4;i++) cp16(As + rowA*36 + segA + i*4, ap + i*4);
        #pragma unroll
        for (int i=0;i<4;i++) cp16(Bs + rowB*136 + segB + i*4, bp + i*4);
        CP_COMMIT();
    }

    for (int c = 0; c < nc; c++){
        CP_WAIT1();
        __syncthreads();
        const int st = c % 3;
        float* As = smf + st*STG_FLOATS;
        float* Bs = As + SM_A;

        if (c+2 < nc){
            const int st2 = (c+2) % 3;
            float* As2 = smf + st2*STG_FLOATS;
            float* Bs2 = As2 + SM_A;
            const float* ap = apBase + (c+2)*32;
            const float* bp = bpBase + (size_t)(c+2)*32*N;
            #pragma unroll
            for (int i=0;i<4;i++) cp16(As2 + rowA*36 + segA + i*4, ap + i*4);
            #pragma unroll
            for (int i=0;i<4;i++) cp16(Bs2 + rowB*136 + segB + i*4, bp + i*4);
        }
        CP_COMMIT();

        #pragma unroll
        for (int ks=0; ks<4; ks++){
            unsigned ahr[4][4], alr[4][4];
            #pragma unroll
            for (int mi=0;mi<4;mi++){
                int r0 = (wm + mi*16 + g)*36 + ks*8 + t4;
                int r1 = r0 + 8*36;
                split1(As[r0],   ahr[mi][0], alr[mi][0]);
                split1(As[r1],   ahr[mi][1], alr[mi][1]);
                split1(As[r0+4], ahr[mi][2], alr[mi][2]);
                split1(As[r1+4], ahr[mi][3], alr[mi][3]);
            }
            #pragma unroll
            for (int ni=0;ni<4;ni++){
                int b0i = (ks*8 + t4)*136 + wn + ni*8 + g;
                int b1i = b0i + 4*136;
                unsigned bh0, bl0, bh1, bl1;
                split1(Bs[b0i], bh0, bl0);
                split1(Bs[b1i], bh1, bl1);
                #pragma unroll
                for (int mi=0;mi<4;mi++){
                    MMA_TF32(acc[mi][ni], ahr[mi][0],ahr[mi][1],ahr[mi][2],ahr[mi][3], bl0,bl1);
                    MMA_TF32(acc[mi][ni], alr[mi][0],alr[mi][1],alr[mi][2],alr[mi][3], bh0,bh1);
                    MMA_TF32(acc[mi][ni], ahr[mi][0],ahr[mi][1],ahr[mi][2],ahr[mi][3], bh0,bh1);
                }
            }
        }
    }

    #pragma unroll
    for (int mi=0;mi<4;mi++){
        #pragma unroll
        for (int half=0; half<2; half++){
            int mm = m0 + wm + mi*16 + g + half*8;
            if (!counts && mm >= M) continue;
            size_t crow = counts ? ((size_t)e*CBSP + mm) : (size_t)mm;
            float* cp = C + crow*N;
            const float* afp = addFull ? (addFull + crow*N) : (const float*)0;
            const float* arp = addRow  ? (addRow + (size_t)(mm % CS)*N) : (const float*)0;
            #pragma unroll
            for (int ni=0;ni<4;ni++){
                int col = n0 + wn + ni*8 + 2*t4;
                float v0 = acc[mi][ni][half*2+0] + bias[col];
                float v1 = acc[mi][ni][half*2+1] + bias[col+1];
                if (arp){ v0 += arp[col]; v1 += arp[col+1]; }
                if (afp){ v0 += afp[col]; v1 += afp[col+1]; }
                if (doGelu){ v0 = gelu_t(v0); v1 = gelu_t(v1); }
                float2 vv; vv.x = v0; vv.y = v1;
                *(float2*)(cp + col) = vv;
            }
        }
    }
}

// =====================================================================
// Dense split-K x3 GEMM, hardcoded N=768, K=768, Ksub=256 (8 chunks).
// =====================================================================
__global__ __launch_bounds__(256,2) void tc_gemm_sk3(
    const float* __restrict__ A,     // [CBS][768]
    const float* __restrict__ W,     // [768][768]
    float* __restrict__ C)           // 3 part images of [CBS][768]
{
    extern __shared__ float smf[];

    const int kp = blockIdx.x / 6;
    const int n0 = (blockIdx.x % 6)*128;
    const int m0 = blockIdx.y*128;
    const int tid = threadIdx.x, wid = tid>>5, lane = tid&31;
    const int wm = (wid>>2)*64;
    const int wn = (wid&3)*32;
    const int g = lane>>2, t4 = lane&3;

    const int rowA = tid>>1, segA = (tid&1)*16;
    const int rowB = tid>>3, segB = (tid&7)*16;

    int mmL = m0 + rowA; if (mmL >= CBS) mmL = CBS-1;
    const float* apBase = A + (size_t)mmL*CD + kp*256 + segA;
    const float* bpBase = W + (size_t)(kp*256 + rowB)*CD + n0 + segB;

    float acc[4][4][4];
    #pragma unroll
    for (int i=0;i<4;i++)
        #pragma unroll
        for (int j=0;j<4;j++)
            #pragma unroll
            for (int q=0;q<4;q++) acc[i][j][q] = 0.f;

    #pragma unroll
    for (int p=0; p<2; p++){
        float* As = smf + p*STG_FLOATS;
        float* Bs = As + SM_A;
        const float* ap = apBase + p*32;
        const float* bp = bpBase + (size_t)p*32*CD;
        #pragma unroll
        for (int i=0;i<4;i++) cp16(As + rowA*36 + segA + i*4, ap + i*4);
        #pragma unroll
        for (int i=0;i<4;i++) cp16(Bs + rowB*136 + segB + i*4, bp + i*4);
        CP_COMMIT();
    }

    for (int c = 0; c < 8; c++){
        CP_WAIT1();
        __syncthreads();
        const int st = c % 3;
        float* As = smf + st*STG_FLOATS;
        float* Bs = As + SM_A;

        if (c+2 < 8){
            const int st2 = (c+2) % 3;
            float* As2 = smf + st2*STG_FLOATS;
            float* Bs2 = As2 + SM_A;
            const float* ap = apBase + (c+2)*32;
            const float* bp = bpBase + (size_t)(c+2)*32*CD;
            #pragma unroll
            for (int i=0;i<4;i++) cp16(As2 + rowA*36 + segA + i*4, ap + i*4);
            #pragma unroll
            for (int i=0;i<4;i++) cp16(Bs2 + rowB*136 + segB + i*4, bp + i*4);
        }
        CP_COMMIT();

        #pragma unroll
        for (int ks=0; ks<4; ks++){
            unsigned ahr[4][4], alr[4][4];
            #pragma unroll
            for (int mi=0;mi<4;mi++){
                int r0 = (wm + mi*16 + g)*36 + ks*8 + t4;
                int r1 = r0 + 8*36;
                split1(As[r0],   ahr[mi][0], alr[mi][0]);
                split1(As[r1],   ahr[mi][1], alr[mi][1]);
                split1(As[r0+4], ahr[mi][2], alr[mi][2]);
                split1(As[r1+4], ahr[mi][3], alr[mi][3]);
            }
            #pragma unroll
            for (int ni=0;ni<4;ni++){
                int b0i = (ks*8 + t4)*136 + wn + ni*8 + g;
                int b1i = b0i + 4*136;
                unsigned bh0, bl0, bh1, bl1;
                split1(Bs[b0i], bh0, bl0);
                split1(Bs[b1i], bh1, bl1);
                #pragma unroll
                for (int mi=0;mi<4;mi++){
                    MMA_TF32(acc[mi][ni], ahr[mi][0],ahr[mi][1],ahr[mi][2],ahr[mi][3], bl0,bl1);
                    MMA_TF32(acc[mi][ni], alr[mi][0],alr[mi][1],alr[mi][2],alr[mi][3], bh0,bh1);
                    MMA_TF32(acc[mi][ni], ahr[mi][0],ahr[mi][1],ahr[mi][2],ahr[mi][3], bh0,bh1);
                }
            }
        }
    }

    float* Cp = C + (size_t)kp*CXPART;
    #pragma unroll
    for (int mi=0;mi<4;mi++){
        #pragma unroll
        for (int half=0; half<2; half++){
            int mm = m0 + wm + mi*16 + g + half*8;
            if (mm >= CBS) continue;
            float* cp = Cp + (size_t)mm*CD;
            #pragma unroll
            for (int ni=0;ni<4;ni++){
                int col = n0 + wn + ni*8 + 2*t4;
                float2 vv; vv.x = acc[mi][ni][half*2+0]; vv.y = acc[mi][ni][half*2+1];
                *(float2*)(cp + col) = vv;
            }
        }
    }
}

// =====================================================================
// w2 expert GEMM, split-K x4 (round 14 winner, unchanged)
// =====================================================================
__global__ __launch_bounds__(256,2) void tc_gemm_w2(
    const float* __restrict__ A,
    const float* __restrict__ Wl,    // [E][3072][768]
    float* __restrict__ C,           // 4 part images
    const int* __restrict__ counts)
{
    extern __shared__ float smf[];

    const int e = blockIdx.z;
    const int Me = counts[e];
    const int m0 = blockIdx.y*128;
    if (m0 >= Me) return;
    const int kp = blockIdx.x / 6;
    const int n0 = (blockIdx.x % 6)*128;
    const int tid = threadIdx.x, wid = tid>>5, lane = tid&31;
    const int wm = (wid>>2)*64;
    const int wn = (wid&3)*32;
    const int g = lane>>2, t4 = lane&3;

    const int rowA = tid>>1, segA = (tid&1)*16;
    const int rowB = tid>>3, segB = (tid&7)*16;

    const float* apBase = A + ((size_t)(e*CBSP + m0 + rowA))*CDF + kp*768 + segA;
    const float* bpBase = Wl + (size_t)e*CDF*CD + ((size_t)(kp*768 + rowB))*CD + n0 + segB;

    float acc[4][4][4];
    #pragma unroll
    for (int i=0;i<4;i++)
        #pragma unroll
        for (int j=0;j<4;j++)
            #pragma unroll
            for (int q=0;q<4;q++) acc[i][j][q] = 0.f;

    #pragma unroll
    for (int p=0; p<2; p++){
        float* As = smf + p*STG_FLOATS;
        float* Bs = As + SM_A;
        const float* ap = apBase + p*32;
        const float* bp = bpBase + (size_t)p*32*CD;
        #pragma unroll
        for (int i=0;i<4;i++) cp16(As + rowA*36 + segA + i*4, ap + i*4);
        #pragma unroll
        for (int i=0;i<4;i++) cp16(Bs + rowB*136 + segB + i*4, bp + i*4);
        CP_COMMIT();
    }

    for (int c = 0; c < 24; c++){
        CP_WAIT1();
        __syncthreads();
        const int st = c % 3;
        float* As = smf + st*STG_FLOATS;
        float* Bs = As + SM_A;

        if (c+2 < 24){
            const int st2 = (c+2) % 3;
            float* As2 = smf + st2*STG_FLOATS;
            float* Bs2 = As2 + SM_A;
            const float* ap = apBase + (c+2)*32;
            const float* bp = bpBase + (size_t)(c+2)*32*CD;
            #pragma unroll
            for (int i=0;i<4;i++) cp16(As2 + rowA*36 + segA + i*4, ap + i*4);
            #pragma unroll
            for (int i=0;i<4;i++) cp16(Bs2 + rowB*136 + segB + i*4, bp + i*4);
        }
        CP_COMMIT();

        #pragma unroll
        for (int ks=0; ks<4; ks++){
            unsigned ahr[4][4], alr[4][4];
            #pragma unroll
            for (int mi=0;mi<4;mi++){
                int r0 = (wm + mi*16 + g)*36 + ks*8 + t4;
                int r1 = r0 + 8*36;
                split1(As[r0],   ahr[mi][0], alr[mi][0]);
                split1(As[r1],   ahr[mi][1], alr[mi][1]);
                split1(As[r0+4], ahr[mi][2], alr[mi][2]);
                split1(As[r1+4], ahr[mi][3], alr[mi][3]);
            }
            #pragma unroll
            for (int ni=0;ni<4;ni++){
                int b0i = (ks*8 + t4)*136 + wn + ni*8 + g;
                int b1i = b0i + 4*136;
                unsigned bh0, bl0, bh1, bl1;
                split1(Bs[b0i], bh0, bl0);
                split1(Bs[b1i], bh1, bl1);
                #pragma unroll
                for (int mi=0;mi<4;mi++){
                    MMA_TF32(acc[mi][ni], ahr[mi][0],ahr[mi][1],ahr[mi][2],ahr[mi][3], bl0,bl1);
                    MMA_TF32(acc[mi][ni], alr[mi][0],alr[mi][1],alr[mi][2],alr[mi][3], bh0,bh1);
                    MMA_TF32(acc[mi][ni], ahr[mi][0],ahr[mi][1],ahr[mi][2],ahr[mi][3], bh0,bh1);
                }
            }
        }
    }

    float* Cp = C + (size_t)kp*CEPART;
    #pragma unroll
    for (int mi=0;mi<4;mi++){
        #pragma unroll
        for (int half=0; half<2; half++){
            int mm = m0 + wm + mi*16 + g + half*8;
            float* cp = Cp + ((size_t)(e*CBSP + mm))*CD;
            #pragma unroll
            for (int ni=0;ni<4;ni++){
                int col = n0 + wn + ni*8 + 2*t4;
                float2 vv; vv.x = acc[mi][ni][half*2+0]; vv.y = acc[mi][ni][half*2+1];
                *(float2*)(cp + col) = vv;
            }
        }
    }
}

// =====================================================================
// Tensor-core flash attention: 32-key chunks, cp.async double buffer,
// ONE barrier per chunk, 4 CTAs/SM preserved (45KB smem).
// 49 chunks cover CS=1568 exactly -> no bounds checks.
// =====================================================================
__global__ __launch_bounds__(128) void attn_tc(const float* __restrict__ qkv,
                                               const float* __restrict__ tb,
                                               float* __restrict__ out){
    extern __shared__ float sm[];
    float* Ps  = sm + ATT_PS;    // [64][36]
    float* tbs = sm + ATT_TBS;

    const int h = blockIdx.y, b = blockIdx.z;
    const int q0 = blockIdx.x*64;
    const int tid = threadIdx.x, w = tid>>5, lane = tid&31;
    const int g = lane>>2, t4 = lane&3;
    const int wm = w*16;

    if (tid < 15) tbs[tid] = tb[h*15 + tid];

    const int row0 = q0 + wm + g, row1 = row0 + 8;
    const int r0c = row0 < CS ? row0 : CS-1;
    const int r1c = row1 < CS ? row1 : CS-1;
    const int fq0 = r0c / CN, fq1 = r1c / CN;

    unsigned qh[8][4], ql[8][4];
    {
        const float* q0p = qkv + (size_t)(b*CS + r0c)*C3D + h*64;
        const float* q1p = qkv + (size_t)(b*CS + r1c)*C3D + h*64;
        #pragma unroll
        for (int ks=0; ks<8; ks++){
            split1(q0p[ks*8+t4]  *0.125f, qh[ks][0], ql[ks][0]);
            split1(q1p[ks*8+t4]  *0.125f, qh[ks][1], ql[ks][1]);
            split1(q0p[ks*8+t4+4]*0.125f, qh[ks][2], ql[ks][2]);
            split1(q1p[ks*8+t4+4]*0.125f, qh[ks][3], ql[ks][3]);
        }
    }

    // prologue: issue chunk 0 into stage 0 (32 keys x 16 float4 x {K,V})
    {
        float* Ks0 = sm + ATT_KS0;
        float* Vs0 = sm + ATT_VS0;
        #pragma unroll
        for (int it=0; it<4; it++){
            int i = tid + it*128;
            int j = i>>4, c4 = (i&15)*4;
            const float* kp_ = qkv + (size_t)(b*CS + j)*C3D + CD + h*64 + c4;
            cp16(Ks0 + j*68 + c4, kp_);
            cp16(Vs0 + j*72 + c4, kp_ + CD);
        }
        CP_COMMIT();
    }

    float o[8][4];
    #pragma unroll
    for (int ni=0;ni<8;ni++){ o[ni][0]=0.f; o[ni][1]=0.f; o[ni][2]=0.f; o[ni][3]=0.f; }
    float m0=-1e30f, m1=-1e30f, l0=0.f, l1=0.f;

    for (int kc = 0; kc < 49; kc++){
        CP_WAIT0();
        __syncthreads();   // chunk kc visible; all warps past compute kc-1
        float* Ks = sm + ((kc&1) ? ATT_KS1 : ATT_KS0);
        float* Vs = sm + ((kc&1) ? ATT_VS1 : ATT_VS0);

        // issue chunk kc+1 into the other stage (safe: its readers finished at the barrier)
        if (kc+1 < 49){
            float* Ks2 = sm + (((kc+1)&1) ? ATT_KS1 : ATT_KS0);
            float* Vs2 = sm + (((kc+1)&1) ? ATT_VS1 : ATT_VS0);
            #pragma unroll
            for (int it=0; it<4; it++){
                int i = tid + it*128;
                int j = i>>4, c4 = (i&15)*4;
                const float* kp_ = qkv + (size_t)(b*CS + (kc+1)*32 + j)*C3D + CD + h*64 + c4;
                cp16(Ks2 + j*68 + c4, kp_);
                cp16(Vs2 + j*72 + c4, kp_ + CD);
            }
        }
        CP_COMMIT();

        // --- QK^T: 32 keys -> 4 ni tiles ---
        float s[4][4];
        #pragma unroll
        for (int ni=0;ni<4;ni++){ s[ni][0]=0.f; s[ni][1]=0.f; s[ni][2]=0.f; s[ni][3]=0.f; }
        #pragma unroll
        for (int ks=0; ks<8; ks++){
            #pragma unroll
            for (int ni=0; ni<4; ni++){
                int kb = (ni*8 + g)*68 + ks*8 + t4;
                unsigned bh0, bl0, bh1, bl1;
                split1(Ks[kb],   bh0, bl0);
                split1(Ks[kb+4], bh1, bl1);
                MMA_TF32(s[ni], qh[ks][0],qh[ks][1],qh[ks][2],qh[ks][3], bl0,bl1);
                MMA_TF32(s[ni], ql[ks][0],ql[ks][1],ql[ks][2],ql[ks][3], bh0,bh1);
                MMA_TF32(s[ni], qh[ks][0],qh[ks][1],qh[ks][2],qh[ks][3], bh0,bh1);
            }
        }

        // --- bias + online softmax (no bounds: 49*32 == CS) ---
        float mx0=-1e30f, mx1=-1e30f;
        #pragma unroll
        for (int ni=0;ni<4;ni++){
            int k0 = kc*32 + ni*8 + 2*t4;
            int fk0 = k0 / CN, fk1 = (k0+1) / CN;
            s[ni][0] += tbs[fq0 - fk0 + 7];
            s[ni][2] += tbs[fq1 - fk0 + 7];
            s[ni][1] += tbs[fq0 - fk1 + 7];
            s[ni][3] += tbs[fq1 - fk1 + 7];
            mx0 = fmaxf(mx0, fmaxf(s[ni][0], s[ni][1]));
            mx1 = fmaxf(mx1, fmaxf(s[ni][2], s[ni][3]));
        }
        mx0 = fmaxf(mx0, __shfl_xor_sync(0xffffffffu, mx0, 1));
        mx0 = fmaxf(mx0, __shfl_xor_sync(0xffffffffu, mx0, 2));
        mx1 = fmaxf(mx1, __shfl_xor_sync(0xffffffffu, mx1, 1));
        mx1 = fmaxf(mx1, __shfl_xor_sync(0xffffffffu, mx1, 2));

        float mn0 = fmaxf(m0, mx0), mn1 = fmaxf(m1, mx1);
        float c0 = __expf(m0 - mn0), c1 = __expf(m1 - mn1);
        float sp0 = 0.f, sp1 = 0.f;
        #pragma unroll
        for (int ni=0;ni<4;ni++){
            s[ni][0] = __expf(s[ni][0] - mn0);
            s[ni][1] = __expf(s[ni][1] - mn0);
            s[ni][2] = __expf(s[ni][2] - mn1);
            s[ni][3] = __expf(s[ni][3] - mn1);
            sp0 += s[ni][0] + s[ni][1];
            sp1 += s[ni][2] + s[ni][3];
            float2 p01; p01.x = s[ni][0]; p01.y = s[ni][1];
            float2 p23; p23.x = s[ni][2]; p23.y = s[ni][3];
            *(float2*)(Ps + (wm+g)*36   + ni*8 + 2*t4) = p01;
            *(float2*)(Ps + (wm+g+8)*36 + ni*8 + 2*t4) = p23;
        }
        sp0 += __shfl_xor_sync(0xffffffffu, sp0, 1);
        sp0 += __shfl_xor_sync(0xffffffffu, sp0, 2);
        sp1 += __shfl_xor_sync(0xffffffffu, sp1, 1);
        sp1 += __shfl_xor_sync(0xffffffffu, sp1, 2);
        l0 = l0*c0 + sp0;  l1 = l1*c1 + sp1;
        m0 = mn0; m1 = mn1;
        #pragma unroll
        for (int ni=0;ni<8;ni++){
            o[ni][0]*=c0; o[ni][1]*=c0; o[ni][2]*=c1; o[ni][3]*=c1;
        }
        __syncwarp();

        // --- P . V: k-dim 32 keys -> 4 ks steps, dh 64 -> 8 ni tiles ---
        #pragma unroll
        for (int ks=0; ks<4; ks++){
            unsigned ah[4], al[4];
            int p0i = (wm+g)*36 + ks*8 + t4;
            int p1i = p0i + 8*36;
            split1(Ps[p0i],   ah[0], al[0]);
            split1(Ps[p1i],   ah[1], al[1]);
            split1(Ps[p0i+4], ah[2], al[2]);
            split1(Ps[p1i+4], ah[3], al[3]);
            #pragma unroll
            for (int ni=0; ni<8; ni++){
                int vb = (ks*8 + t4)*72 + ni*8 + g;
                unsigned bh0, bl0, bh1, bl1;
                split1(Vs[vb],      bh0, bl0);
                split1(Vs[vb+4*72], bh1, bl1);
                MMA_TF32(o[ni], ah[0],ah[1],ah[2],ah[3], bl0,bl1);
                MMA_TF32(o[ni], al[0],al[1],al[2],al[3], bh0,bh1);
                MMA_TF32(o[ni], ah[0],ah[1],ah[2],ah[3], bh0,bh1);
            }
        }
    }

    float inv0 = 1.f/l0, inv1 = 1.f/l1;
    if (row0 < CS){
        float* op = out + (size_t)(b*CS + row0)*CD + h*64;
        #pragma unroll
        for (int ni=0;ni<8;ni++){
            float2 vv; vv.x = o[ni][0]*inv0; vv.y = o[ni][1]*inv0;
            *(float2*)(op + ni*8 + 2*t4) = vv;
        }
    }
    if (row1 < CS){
        float* op = out + (size_t)(b*CS + row1)*CD + h*64;
        #pragma unroll
        for (int ni=0;ni<8;ni++){
            float2 vv; vv.x = o[ni][2]*inv1; vv.y = o[ni][3]*inv1;
            *(float2*)(op + ni*8 + 2*t4) = vv;
        }
    }
}

// ---------------- text projection (tiny) ----------------
__global__ __launch_bounds__(256) void textproj_k(const float* __restrict__ ts,
                                                  const float* __restrict__ wt,
                                                  const float* __restrict__ bt,
                                                  float* __restrict__ out){
    int i = blockIdx.x*256 + threadIdx.x;
    if (i >= CB*CD) return;
    int b = i/CD, d = i%CD;
    float a = bt[d];
    for (int k=0;k<CD;k++) a += ts[b*CD+k]*wt[(size_t)k*CD+d];
    out[i] = a;
}

__global__ void zero8_k(int* c){ if (threadIdx.x < CE) c[threadIdx.x] = 0; }

// ---------------- router ----------------
__global__ __launch_bounds__(256) void router_k(const float* __restrict__ h2,
                                                const float* __restrict__ tproj,
                                                const float* __restrict__ wr,
                                                int* __restrict__ counts,
                                                int* __restrict__ tok_of_slot,
                                                int* __restrict__ slot_of,
                                                float* __restrict__ gatev){
    int w = threadIdx.x >> 5, lane = threadIdx.x & 31;
    int r = blockIdx.x*8 + w;
    int b = r / CS;
    float acc[8] = {};
    for (int d = lane; d < CD; d += 32){
        float rv = h2[(size_t)r*CD + d] + tproj[b*CD + d];
        #pragma unroll
        for (int e=0;e<8;e++) acc[e] += rv * wr[d*8 + e];
    }
    #pragma unroll
    for (int e=0;e<8;e++)
        #pragma unroll
        for (int o=16;o;o>>=1) acc[e] += __shfl_xor_sync(0xffffffffu, acc[e], o);
    if (lane == 0){
        int i0 = 0; float v0 = acc[0];
        #pragma unroll
        for (int e=1;e<8;e++) if (acc[e] > v0){ v0=acc[e]; i0=e; }
        int i1 = -1; float v1 = -1e30f;
        #pragma unroll
        for (int e=0;e<8;e++) if (e!=i0 && acc[e] > v1){ v1=acc[e]; i1=e; }
        float g0 = 1.f/(1.f + expf(v1 - v0));
        float g1 = 1.f - g0;
        int p0 = atomicAdd(&counts[i0], 1);
        tok_of_slot[i0*CBS + p0] = r; slot_of[r*2]   = i0*CBSP + p0; gatev[r*2]   = g0;
        int p1 = atomicAdd(&counts[i1], 1);
        tok_of_slot[i1*CBS + p1] = r; slot_of[r*2+1] = i1*CBSP + p1; gatev[r*2+1] = g1;
    }
}

// =============================== host ===============================
extern "C" void kernel_launch(void* const* d_in, const int* in_sizes, int n_in,
                              void* d_out, int out_size){
    const float* video   = (const float*)d_in[0];
    const float* text    = (const float*)d_in[1];
    const float* patch_w = (const float*)d_in[2];
    const float* patch_b = (const float*)d_in[3];
    const float* pos_emb = (const float*)d_in[4];
    const float* ln1s    = (const float*)d_in[5];
    const float* ln1b    = (const float*)d_in[6];
    const float* wqkv    = (const float*)d_in[7];
    const float* bqkv    = (const float*)d_in[8];
    const float* wo      = (const float*)d_in[9];
    const float* bo      = (const float*)d_in[10];
    const float* tbias   = (const float*)d_in[11];
    const float* ln2s    = (const float*)d_in[12];
    const float* ln2b    = (const float*)d_in[13];
    const float* wtext   = (const float*)d_in[14];
    const float* btext   = (const float*)d_in[15];
    const float* wrouter = (const float*)d_in[16];
    const float* w1      = (const float*)d_in[17];
    const float* b1      = (const float*)d_in[18];
    const float* w2      = (const float*)d_in[19];
    const float* b2      = (const float*)d_in[20];
    const float* lnfs    = (const float*)d_in[21];
    const float* lnfb    = (const float*)d_in[22];

    float *p_patches,*p_x,*p_h,*p_h2,*p_qkv,*p_att,*p_he,*p_moe4,*p_p3,*p_tproj,*p_gate;
    int *p_counts,*p_tok,*p_slot;
    cudaGetSymbolAddress((void**)&p_patches, g_patches);
    cudaGetSymbolAddress((void**)&p_x,       g_x);
    cudaGetSymbolAddress((void**)&p_h,       g_h);
    cudaGetSymbolAddress((void**)&p_h2,      g_h2);
    cudaGetSymbolAddress((void**)&p_qkv,     g_qkv);
    cudaGetSymbolAddress((void**)&p_att,     g_att);
    cudaGetSymbolAddress((void**)&p_he,      g_he);
    cudaGetSymbolAddress((void**)&p_moe4,    g_moe4);
    cudaGetSymbolAddress((void**)&p_p3,      g_p3);
    cudaGetSymbolAddress((void**)&p_tproj,   g_tproj);
    cudaGetSymbolAddress((void**)&p_counts,  g_counts);
    cudaGetSymbolAddress((void**)&p_tok,     g_tok);
    cudaGetSymbolAddress((void**)&p_slot,    g_slot);
    cudaGetSymbolAddress((void**)&p_gate,    g_gate);

    cudaFuncSetAttribute(tc_gemm, cudaFuncAttributeMaxDynamicSharedMemorySize, TC_SMEM_BYTES);
    cudaFuncSetAttribute(tc_gemm_sk3, cudaFuncAttributeMaxDynamicSharedMemorySize, TC_SMEM_BYTES);
    cudaFuncSetAttribute(tc_gemm_w2, cudaFuncAttributeMaxDynamicSharedMemorySize, TC_SMEM_BYTES);
    cudaFuncSetAttribute(attn_tc, cudaFuncAttributeMaxDynamicSharedMemorySize, ATT_SMEM_BYTES);

    const int EW = (CBS*CD + 255)/256;
    const int MB = (CBS + 127)/128;      // 25
    const int QB = (CS + 63)/64;         // 25

    // embed: split-K x3 -> p_p3; fused epilogue: x = sum+bias+pos, h = LN1_0(x)
    patchify_k<<<EW,256>>>(video, p_patches);
    tc_gemm_sk3<<<dim3(18, MB, 1),256,TC_SMEM_BYTES>>>(p_patches, patch_w, p_p3);
    add3e_ln_k<<<CBS,256>>>(p_x, p_p3, patch_b, pos_emb, ln1s, ln1b, p_h);

    for (int l = 0; l < 4; l++){
        // attention
        tc_gemm<<<dim3(C3D/128, MB, 1),256,TC_SMEM_BYTES>>>(
            CBS, C3D, CD, p_h, wqkv + (size_t)l*CD*C3D, 0, bqkv + l*C3D, 0,
            nullptr, nullptr, p_qkv, nullptr, nullptr, 0);
        attn_tc<<<dim3(QB, CHEADS, CB),128,ATT_SMEM_BYTES>>>(
            p_qkv, tbias + l*CHEADS*(2*CT-1), p_att);
        // WO: split-K x3; fused epilogue: x += sum+bias, h2 = LN2_l(x)
        tc_gemm_sk3<<<dim3(18, MB, 1),256,TC_SMEM_BYTES>>>(
            p_att, wo + (size_t)l*CD*CD, p_p3);
        add3r_ln_k<<<CBS,256>>>(p_x, p_p3, bo + l*CD, ln2s + l*CD, ln2b + l*CD, p_h2);
        // MoE
        textproj_k<<<(CB*CD+255)/256,256>>>(text, wtext + (size_t)l*CD*CD, btext + l*CD, p_tproj);
        zero8_k<<<1,CE>>>(p_counts);
        router_k<<<CBS/8,256>>>(p_h2, p_tproj, wrouter + (size_t)l*CD*CE,
                                p_counts, p_tok, p_slot, p_gate);
        tc_gemm<<<dim3(CDF/128, MB, CE),256,TC_SMEM_BYTES>>>(
            CBS, CDF, CD, p_h2, w1 + (size_t)l*CE*CD*CDF, (size_t)CD*CDF,
            b1 + (size_t)l*CE*CDF, CDF,
            nullptr, nullptr, p_he, p_tok, p_counts, 1);
        tc_gemm_w2<<<dim3(4*6, MB, CE),256,TC_SMEM_BYTES>>>(
            p_he, w2 + (size_t)l*CE*CDF*CD, p_moe4, p_counts);
        // fused combine + next LN (lnf on last layer, writing d_out)
        if (l < 3){
            combine4_ln_k<<<CBS,256>>>(p_x, p_moe4, b2 + (size_t)l*CE*CD, p_slot, p_gate,
                                       ln1s + (l+1)*CD, ln1b + (l+1)*CD, p_h);
        } else {
            combine4_ln_k<<<CBS,256>>>(p_x, p_moe4, b2 + (size_t)l*CE*CD, p_slot, p_gate,
                                       lnfs, lnfb, (float*)d_out);
        }
    }
}